// round 11
// baseline (speedup 1.0000x reference)
#include <cuda_runtime.h>
#include <cuda_bf16.h>
#include <cstdint>

#define NPTS 80000
#define NBH  32
#define KPN  15
#define CIN  128
#define D2   64
#define COUT 256
#define FKDIM (KPN*D2)   /* 960 */
#define INV_INFL 2.5f
#define EPSBN 1e-5f
#define SLOPE 0.2f

typedef __nv_bfloat16 bf16;

/* ------------------------- device scratch ------------------------------- */
/* Referenced ONLY from device code (host-side &__device__ = ATS trap). */
__device__ float g_x1[(size_t)NPTS*D2];
__device__ float g_sc[(size_t)NPTS*COUT];
__device__ bf16  g_feats_hi[(size_t)NPTS*CIN], g_feats_lo[(size_t)NPTS*CIN];
__device__ bf16  g_fk_hi[(size_t)NPTS*FKDIM], g_fk_lo[(size_t)NPTS*FKDIM];
__device__ bf16  g_xmid_hi[(size_t)NPTS*D2],  g_xmid_lo[(size_t)NPTS*D2];

__device__ bf16 g_W1t_hi[D2*CIN],   g_W1t_lo[D2*CIN];
__device__ bf16 g_Wsct_hi[COUT*CIN],g_Wsct_lo[COUT*CIN];
__device__ bf16 g_kpwt_hi[D2*FKDIM],g_kpwt_lo[D2*FKDIM];
__device__ bf16 g_W2t_hi[COUT*D2],  g_W2t_lo[COUT*D2];

__device__ float g_sum1[D2],  g_sq1[D2],  g_scale1[D2],  g_shift1[D2];
__device__ float g_sumsc[COUT],g_sqsc[COUT],g_scalesc[COUT],g_shiftsc[COUT];
__device__ float g_sum2[COUT], g_sq2[COUT], g_scale2[COUT], g_shift2[COUT];

/* ------------------------- ptx helpers ---------------------------------- */
__device__ __forceinline__ void mma16816(float* c, const uint32_t* a, const uint32_t* b) {
    asm volatile("mma.sync.aligned.m16n8k16.row.col.f32.bf16.bf16.f32 "
        "{%0,%1,%2,%3}, {%4,%5,%6,%7}, {%8,%9}, {%0,%1,%2,%3};"
        : "+f"(c[0]), "+f"(c[1]), "+f"(c[2]), "+f"(c[3])
        : "r"(a[0]), "r"(a[1]), "r"(a[2]), "r"(a[3]), "r"(b[0]), "r"(b[1]));
}
__device__ __forceinline__ uint32_t ld32s(const bf16* p) {
    return *reinterpret_cast<const uint32_t*>(p);
}
__device__ __forceinline__ void cpasync16(void* s, const void* g) {
    uint32_t sa = (uint32_t)__cvta_generic_to_shared(s);
    asm volatile("cp.async.ca.shared.global [%0], [%1], 16;" :: "r"(sa), "l"(g) : "memory");
}
#define CP_COMMIT() asm volatile("cp.async.commit_group;" ::: "memory")
#define CP_WAIT1()  asm volatile("cp.async.wait_group 1;" ::: "memory")
#define CP_WAIT0()  asm volatile("cp.async.wait_group 0;" ::: "memory")

/* ------------------------- misc small kernels --------------------------- */
__global__ void k_zero() {
    int t = threadIdx.x;
    if (t < D2) { g_sum1[t] = 0.f; g_sq1[t] = 0.f; }
    g_sumsc[t] = 0.f; g_sqsc[t] = 0.f;
    g_sum2[t]  = 0.f; g_sq2[t]  = 0.f;
}

__device__ __forceinline__ void split_store(float v, bf16* hi, bf16* lo, size_t i) {
    bf16 h = __float2bfloat16(v);
    hi[i] = h;
    lo[i] = __float2bfloat16(v - __bfloat162float(h));
}

__global__ __launch_bounds__(256) void k_prep_feats(const float* __restrict__ f) {
    int i4 = blockIdx.x * 256 + threadIdx.x;            /* < 2,560,000 */
    float4 v = ((const float4*)f)[i4];
    bf16 h0 = __float2bfloat16(v.x), h1 = __float2bfloat16(v.y);
    bf16 h2 = __float2bfloat16(v.z), h3 = __float2bfloat16(v.w);
    union { bf16 b[4]; uint2 u; } H, L;
    H.b[0] = h0; H.b[1] = h1; H.b[2] = h2; H.b[3] = h3;
    L.b[0] = __float2bfloat16(v.x - __bfloat162float(h0));
    L.b[1] = __float2bfloat16(v.y - __bfloat162float(h1));
    L.b[2] = __float2bfloat16(v.z - __bfloat162float(h2));
    L.b[3] = __float2bfloat16(v.w - __bfloat162float(h3));
    ((uint2*)g_feats_hi)[i4] = H.u;
    ((uint2*)g_feats_lo)[i4] = L.u;
}

__global__ __launch_bounds__(256) void k_prep_w(const float* __restrict__ W1,
                                                const float* __restrict__ Wsc,
                                                const float* __restrict__ kpw,
                                                const float* __restrict__ W2)
{
    int i = blockIdx.x * 256 + threadIdx.x;             /* < 118784 */
    if (i < 8192) {                                     /* W1t [64,128] */
        int e = i >> 7, k = i & 127;
        split_store(W1[k * D2 + e], g_W1t_hi, g_W1t_lo, i);
    } else if (i < 40960) {                             /* Wsct [256,128] */
        int j = i - 8192; int e = j >> 7, k = j & 127;
        split_store(Wsc[k * COUT + e], g_Wsct_hi, g_Wsct_lo, j);
    } else if (i < 102400) {                            /* kpwt [64,960] */
        int j = i - 40960; int e = j / FKDIM, kd = j % FKDIM;
        split_store(kpw[(size_t)kd * D2 + e], g_kpwt_hi, g_kpwt_lo, j);
    } else {                                            /* W2t [256,64] */
        int j = i - 102400; int e = j >> 6, k = j & 63;
        split_store(W2[k * COUT + e], g_W2t_hi, g_W2t_lo, j);
    }
}

__device__ __forceinline__ void fin_body(const float* sum, const float* sq,
                                         const float* g, const float* b,
                                         float* scale, float* shift)
{
    int c = threadIdx.x;
    float m = sum[c] * (1.0f / NPTS);
    float v = sq[c] * (1.0f / NPTS) - m * m;
    float s = g[c] * rsqrtf(v + EPSBN);
    scale[c] = s;
    shift[c] = b[c] - m * s;
}
__global__ void k_fin1(const float* g, const float* b)  { fin_body(g_sum1, g_sq1, g, b, g_scale1, g_shift1); }
__global__ void k_finsc(const float* g, const float* b) { fin_body(g_sumsc, g_sqsc, g, b, g_scalesc, g_shiftsc); }
__global__ void k_fin2(const float* g, const float* b)  { fin_body(g_sum2, g_sq2, g, b, g_scale2, g_shift2); }

/* ------------------------- HMMA split-bf16 GEMM + cp.async pipeline ------ */
/* Tile 128x64, 256 thr = 8 warps (4 m x 2 n), warp tile 32x32.
   VERIFIED fragment addressing + double-buffered cp.async + fused BN stats.
   D = Ah*Bh + Ah*Bl + Al*Bh (fp32 accum).
   MODE 0: fp32 C + stats.  MODE 1: split bf16 hi/lo C (ld 64). */
#define AST 40
#define BUF_ELEMS 15360
#define OFF_AL 5120
#define OFF_BH 10240
#define OFF_BL 12800
#define GEMM_SMEM 61440

template<int KTOT, int MODE>
__device__ __forceinline__ void mmagemm_body(
    const bf16* __restrict__ Ahi, const bf16* __restrict__ Alo,
    const bf16* __restrict__ Bhi, const bf16* __restrict__ Blo,
    float* __restrict__ Cf, int ldc,
    bf16* __restrict__ Chi, bf16* __restrict__ Clo,
    float* __restrict__ sumP, float* __restrict__ sqP)
{
    extern __shared__ __align__(16) bf16 smem[];

    const int t = threadIdx.x, lane = t & 31, wid = t >> 5;
    const int wm = wid & 3, wn = wid >> 2;
    const int m0 = blockIdx.x * 128, n0 = blockIdx.y * 64;
    const int gr = lane >> 2, gc2 = (lane & 3) * 2;

    const int arow0 = t >> 2, ac8 = (t & 3) * 8;
    const int brow = t >> 2,  bc8 = (t & 3) * 8;

    float acc[2][4][4];
#pragma unroll
    for (int i = 0; i < 2; i++)
#pragma unroll
        for (int j = 0; j < 4; j++)
#pragma unroll
            for (int q = 0; q < 4; q++) acc[i][j][q] = 0.f;

    constexpr int NCH = KTOT / 32;

    auto issue = [&](int kc) {
        bf16* buf = smem + (kc & 1) * BUF_ELEMS;
#pragma unroll
        for (int it = 0; it < 2; it++) {
            int row = arow0 + it * 64;
            size_t gsrc = (size_t)(m0 + row) * KTOT + kc * 32 + ac8;
            cpasync16(buf + row * AST + ac8, Ahi + gsrc);
            cpasync16(buf + OFF_AL + row * AST + ac8, Alo + gsrc);
        }
        {
            size_t gsrc = (size_t)(n0 + brow) * KTOT + kc * 32 + bc8;
            cpasync16(buf + OFF_BH + brow * AST + bc8, Bhi + gsrc);
            cpasync16(buf + OFF_BL + brow * AST + bc8, Blo + gsrc);
        }
        CP_COMMIT();
    };

    issue(0);

    for (int kc = 0; kc < NCH; kc++) {
        if (kc + 1 < NCH) { issue(kc + 1); CP_WAIT1(); }
        else              { CP_WAIT0(); }
        __syncthreads();

        const bf16* sAh = smem + (kc & 1) * BUF_ELEMS;
        const bf16* sAl = sAh + OFF_AL;
        const bf16* sBh = sAh + OFF_BH;
        const bf16* sBl = sAh + OFF_BL;

#pragma unroll
        for (int kk = 0; kk < 2; kk++) {
            const int kb = kk * 16;
            uint32_t ah[2][4], al[2][4], bh[4][2], bl[4][2];
#pragma unroll
            for (int mt = 0; mt < 2; mt++) {
                const bf16* ph = sAh + (wm * 32 + mt * 16 + gr) * AST + kb + gc2;
                ah[mt][0] = ld32s(ph);
                ah[mt][1] = ld32s(ph + 8 * AST);
                ah[mt][2] = ld32s(ph + 8);
                ah[mt][3] = ld32s(ph + 8 * AST + 8);
                const bf16* pl = sAl + (wm * 32 + mt * 16 + gr) * AST + kb + gc2;
                al[mt][0] = ld32s(pl);
                al[mt][1] = ld32s(pl + 8 * AST);
                al[mt][2] = ld32s(pl + 8);
                al[mt][3] = ld32s(pl + 8 * AST + 8);
            }
#pragma unroll
            for (int nt = 0; nt < 4; nt++) {
                const bf16* ph = sBh + (wn * 32 + nt * 8 + gr) * AST + kb + gc2;
                bh[nt][0] = ld32s(ph);
                bh[nt][1] = ld32s(ph + 8);
                const bf16* pl = sBl + (wn * 32 + nt * 8 + gr) * AST + kb + gc2;
                bl[nt][0] = ld32s(pl);
                bl[nt][1] = ld32s(pl + 8);
            }
#pragma unroll
            for (int mt = 0; mt < 2; mt++)
#pragma unroll
                for (int nt = 0; nt < 4; nt++) {
                    mma16816(acc[mt][nt], ah[mt], bh[nt]);
                    mma16816(acc[mt][nt], ah[mt], bl[nt]);
                    mma16816(acc[mt][nt], al[mt], bh[nt]);
                }
        }
        __syncthreads();
    }

    const int rbase = m0 + wm * 32 + gr;
    const int cbase = wn * 32 + gc2;

    if (MODE == 0) {
#pragma unroll
        for (int mt = 0; mt < 2; mt++)
#pragma unroll
            for (int nt = 0; nt < 4; nt++) {
                int r0 = rbase + mt * 16, r1 = r0 + 8;
                int cc = n0 + cbase + nt * 8;
                *(float2*)(Cf + (size_t)r0 * ldc + cc) =
                    make_float2(acc[mt][nt][0], acc[mt][nt][1]);
                *(float2*)(Cf + (size_t)r1 * ldc + cc) =
                    make_float2(acc[mt][nt][2], acc[mt][nt][3]);
            }

        float cs[8], cq[8];
#pragma unroll
        for (int nt = 0; nt < 4; nt++)
#pragma unroll
            for (int j = 0; j < 2; j++) {
                float v0 = acc[0][nt][j],     v1 = acc[0][nt][2 + j];
                float v2 = acc[1][nt][j],     v3 = acc[1][nt][2 + j];
                cs[nt * 2 + j] = v0 + v1 + v2 + v3;
                cq[nt * 2 + j] = v0 * v0 + v1 * v1 + v2 * v2 + v3 * v3;
            }
#pragma unroll
        for (int off = 4; off < 32; off <<= 1)
#pragma unroll
            for (int i = 0; i < 8; i++) {
                cs[i] += __shfl_xor_sync(0xffffffffu, cs[i], off);
                cq[i] += __shfl_xor_sync(0xffffffffu, cq[i], off);
            }

        float* fs = (float*)smem;
        if (t < 128) fs[t] = 0.f;
        __syncthreads();
        if ((lane & 28) == 0) {
#pragma unroll
            for (int nt = 0; nt < 4; nt++)
#pragma unroll
                for (int j = 0; j < 2; j++) {
                    int col = wn * 32 + (lane & 3) * 2 + nt * 8 + j;
                    atomicAdd(&fs[col],      cs[nt * 2 + j]);
                    atomicAdd(&fs[64 + col], cq[nt * 2 + j]);
                }
        }
        __syncthreads();
        if (t < 64) {
            atomicAdd(&sumP[n0 + t], fs[t]);
            atomicAdd(&sqP[n0 + t],  fs[64 + t]);
        }
    } else {
#pragma unroll
        for (int mt = 0; mt < 2; mt++)
#pragma unroll
            for (int nt = 0; nt < 4; nt++) {
                int cc = n0 + cbase + nt * 8;
#pragma unroll
                for (int half = 0; half < 2; half++) {
                    int rr = rbase + mt * 16 + half * 8;
                    float v0 = acc[mt][nt][half * 2 + 0];
                    float v1 = acc[mt][nt][half * 2 + 1];
                    union { bf16 b[2]; uint32_t u; } H, L;
                    bf16 h0 = __float2bfloat16(v0), h1 = __float2bfloat16(v1);
                    H.b[0] = h0; H.b[1] = h1;
                    L.b[0] = __float2bfloat16(v0 - __bfloat162float(h0));
                    L.b[1] = __float2bfloat16(v1 - __bfloat162float(h1));
                    *(uint32_t*)(Chi + (size_t)rr * 64 + cc) = H.u;
                    *(uint32_t*)(Clo + (size_t)rr * 64 + cc) = L.u;
                }
            }
    }
}

/* wrappers: globals bound in DEVICE code */
__global__ __launch_bounds__(256) void k_gemm_u1() {
    mmagemm_body<128, 0>(g_feats_hi, g_feats_lo, g_W1t_hi, g_W1t_lo,
                         g_x1, D2, nullptr, nullptr, g_sum1, g_sq1);
}
__global__ __launch_bounds__(256) void k_gemm_sc() {
    mmagemm_body<128, 0>(g_feats_hi, g_feats_lo, g_Wsct_hi, g_Wsct_lo,
                         g_sc, COUT, nullptr, nullptr, g_sumsc, g_sqsc);
}
__global__ __launch_bounds__(256) void k_gemm_fk() {
    mmagemm_body<960, 1>(g_fk_hi, g_fk_lo, g_kpwt_hi, g_kpwt_lo,
                         nullptr, 0, g_xmid_hi, g_xmid_lo, nullptr, nullptr);
}
__global__ __launch_bounds__(256) void k_gemm_u2(float* __restrict__ out) {
    mmagemm_body<64, 0>(g_xmid_hi, g_xmid_lo, g_W2t_hi, g_W2t_lo,
                        out, COUT, nullptr, nullptr, g_sum2, g_sq2);
}

/* ------------------------- KPConv (sparse influence) -------------------- */
__device__ __forceinline__ float fsqrt_approx(float x) {
    float r; asm("sqrt.approx.f32 %0, %1;" : "=f"(r) : "f"(x)); return r;
}

__global__ __launch_bounds__(256) void k_kpconv(const float* __restrict__ xyz,
                                                const int* __restrict__ nidx,
                                                const float* __restrict__ kp)
{
    __shared__ float kps[KPN][3];
    __shared__ float ws[8][NBH][KPN];
    const int t = threadIdx.x;
    if (t < KPN * 3) ((float*)kps)[t] = kp[t];
    __syncthreads();

    const int warp = t >> 5, lane = t & 31;
    const int n = blockIdx.x * 8 + warp;

    const float cx = xyz[n * 3 + 0], cy = xyz[n * 3 + 1], cz = xyz[n * 3 + 2];
    const int j = nidx[n * NBH + lane];
    const float rx = xyz[j * 3 + 0] - cx;
    const float ry = xyz[j * 3 + 1] - cy;
    const float rz = xyz[j * 3 + 2] - cz;

    unsigned mask = 0;
#pragma unroll
    for (int k = 0; k < KPN; k++) {
        float dx = rx - kps[k][0], dy = ry - kps[k][1], dz = rz - kps[k][2];
        float sq = dx * dx + dy * dy + dz * dz;
        float w = 1.0f - fsqrt_approx(sq) * INV_INFL;
        w = w > 0.f ? w : 0.f;
        ws[warp][lane][k] = w;
        if (w > 0.f) mask |= (1u << k);
    }
    __syncwarp();

    const float sc0 = g_scale1[2 * lane], sc1 = g_scale1[2 * lane + 1];
    const float sh0 = g_shift1[2 * lane], sh1 = g_shift1[2 * lane + 1];
    const float2* x1v = (const float2*)g_x1;

    float fk0[KPN], fk1[KPN];
#pragma unroll
    for (int k = 0; k < KPN; k++) { fk0[k] = 0.f; fk1[k] = 0.f; }

    for (int h = 0; h < NBH; h++) {
        unsigned mh = __shfl_sync(0xffffffffu, mask, h);
        if (!mh) continue;                                 /* warp-uniform */
        int jj = __shfl_sync(0xffffffffu, j, h);
        float2 v = x1v[(size_t)jj * 32 + lane];
        float a = v.x * sc0 + sh0; a = a > 0.f ? a : SLOPE * a;
        float b = v.y * sc1 + sh1; b = b > 0.f ? b : SLOPE * b;
        while (mh) {
            int k = __ffs(mh) - 1; mh &= mh - 1;
            float w = ws[warp][h][k];
            fk0[k] += w * a;
            fk1[k] += w * b;
        }
    }

    bf16* oh = g_fk_hi + (size_t)n * FKDIM;
    bf16* ol = g_fk_lo + (size_t)n * FKDIM;
#pragma unroll
    for (int k = 0; k < KPN; k++) {
        union { bf16 b[2]; uint32_t u; } H, L;
        bf16 h0 = __float2bfloat16(fk0[k]), h1 = __float2bfloat16(fk1[k]);
        H.b[0] = h0; H.b[1] = h1;
        L.b[0] = __float2bfloat16(fk0[k] - __bfloat162float(h0));
        L.b[1] = __float2bfloat16(fk1[k] - __bfloat162float(h1));
        *(uint32_t*)(oh + k * 64 + 2 * lane) = H.u;
        *(uint32_t*)(ol + k * 64 + 2 * lane) = L.u;
    }
}

/* ------------------------- final epilogue — known good ------------------- */
__global__ __launch_bounds__(256) void k_epilogue(float* __restrict__ out)
{
    __shared__ float s2[COUT], h2[COUT], ss[COUT], hs[COUT];
    const int t = threadIdx.x;
    s2[t] = g_scale2[t];  h2[t] = g_shift2[t];
    ss[t] = g_scalesc[t]; hs[t] = g_shiftsc[t];
    __syncthreads();

    const int idx = blockIdx.x * 256 + t;          /* float4 index */
    const int c4 = (idx & 63) * 4;

    float4 x = ((float4*)out)[idx];
    float4 s = ((const float4*)g_sc)[idx];
    float v0 = x.x * s2[c4 + 0] + h2[c4 + 0]; v0 = v0 > 0.f ? v0 : SLOPE * v0;
    float v1 = x.y * s2[c4 + 1] + h2[c4 + 1]; v1 = v1 > 0.f ? v1 : SLOPE * v1;
    float v2 = x.z * s2[c4 + 2] + h2[c4 + 2]; v2 = v2 > 0.f ? v2 : SLOPE * v2;
    float v3 = x.w * s2[c4 + 3] + h2[c4 + 3]; v3 = v3 > 0.f ? v3 : SLOPE * v3;
    float4 r;
    r.x = v0 + s.x * ss[c4 + 0] + hs[c4 + 0];
    r.y = v1 + s.y * ss[c4 + 1] + hs[c4 + 1];
    r.z = v2 + s.z * ss[c4 + 2] + hs[c4 + 2];
    r.w = v3 + s.w * ss[c4 + 3] + hs[c4 + 3];
    ((float4*)out)[idx] = r;
}

/* ------------------------- launch ---------------------------------------- */
extern "C" void kernel_launch(void* const* d_in, const int* in_sizes, int n_in,
                              void* d_out, int out_size)
{
    const float* feats = (const float*)d_in[0];
    const float* xyz   = (const float*)d_in[1];
    const int*   nidx  = (const int*)d_in[3];
    const float* W1    = (const float*)d_in[4];
    const float* g1    = (const float*)d_in[5];
    const float* b1    = (const float*)d_in[6];
    const float* kp    = (const float*)d_in[7];
    const float* kpw   = (const float*)d_in[8];
    const float* W2    = (const float*)d_in[9];
    const float* g2    = (const float*)d_in[10];
    const float* b2    = (const float*)d_in[11];
    const float* Wsc   = (const float*)d_in[12];
    const float* gsc   = (const float*)d_in[13];
    const float* bsc   = (const float*)d_in[14];
    float* out = (float*)d_out;

    static cudaStream_t s2 = nullptr;
    static cudaEvent_t evPrep = nullptr, evSc = nullptr;
    if (s2 == nullptr) {
        cudaFuncSetAttribute(k_gemm_u1, cudaFuncAttributeMaxDynamicSharedMemorySize, GEMM_SMEM);
        cudaFuncSetAttribute(k_gemm_sc, cudaFuncAttributeMaxDynamicSharedMemorySize, GEMM_SMEM);
        cudaFuncSetAttribute(k_gemm_fk, cudaFuncAttributeMaxDynamicSharedMemorySize, GEMM_SMEM);
        cudaFuncSetAttribute(k_gemm_u2, cudaFuncAttributeMaxDynamicSharedMemorySize, GEMM_SMEM);
        cudaStreamCreateWithFlags(&s2, cudaStreamNonBlocking);
        cudaEventCreateWithFlags(&evPrep, cudaEventDisableTiming);
        cudaEventCreateWithFlags(&evSc, cudaEventDisableTiming);
    }

    /* ---- prep (default stream) ---- */
    k_zero<<<1, 256>>>();
    k_prep_feats<<<(NPTS * CIN / 4) / 256, 256>>>(feats);
    k_prep_w<<<464, 256>>>(W1, Wsc, kpw, W2);
    cudaEventRecord(evPrep, 0);

    /* ---- shortcut branch on s2 (only epilogue depends on it) ---- */
    cudaStreamWaitEvent(s2, evPrep, 0);
    k_gemm_sc<<<dim3(NPTS / 128, 4), 256, GEMM_SMEM, s2>>>();
    k_finsc<<<1, COUT, 0, s2>>>(gsc, bsc);
    cudaEventRecord(evSc, s2);

    /* ---- main chain (default stream) ---- */
    k_gemm_u1<<<dim3(NPTS / 128, 1), 256, GEMM_SMEM>>>();
    k_fin1<<<1, D2>>>(g1, b1);

    k_kpconv<<<NPTS / 8, 256>>>(xyz, nidx, kp);

    k_gemm_fk<<<dim3(NPTS / 128, 1), 256, GEMM_SMEM>>>();
    k_gemm_u2<<<dim3(NPTS / 128, 4), 256, GEMM_SMEM>>>(out);
    k_fin2<<<1, COUT>>>(g2, b2);

    /* epilogue needs the shortcut branch */
    cudaStreamWaitEvent(0, evSc, 0);
    k_epilogue<<<(NPTS * (COUT / 4)) / 256, 256>>>(out);
}

// round 12
// speedup vs baseline: 1.4851x; 1.4851x over previous
#include <cuda_runtime.h>
#include <cuda_bf16.h>
#include <cstdint>

#define NPTS 80000
#define NBH  32
#define KPN  15
#define CIN  128
#define D2   64
#define COUT 256
#define FKDIM (KPN*D2)   /* 960 */
#define INV_INFL 2.5f
#define EPSBN 1e-5f
#define SLOPE 0.2f

typedef __nv_bfloat16 bf16;

/* ------------------------- device scratch ------------------------------- */
/* Referenced ONLY from device code (host-side &__device__ = ATS trap). */
__device__ float g_x1[(size_t)NPTS*D2];
__device__ float g_sc[(size_t)NPTS*COUT];
__device__ bf16  g_feats_hi[(size_t)NPTS*CIN], g_feats_lo[(size_t)NPTS*CIN];
__device__ bf16  g_fk_hi[(size_t)NPTS*FKDIM], g_fk_lo[(size_t)NPTS*FKDIM];
__device__ bf16  g_xmid_hi[(size_t)NPTS*D2],  g_xmid_lo[(size_t)NPTS*D2];

__device__ bf16 g_W1t_hi[D2*CIN],   g_W1t_lo[D2*CIN];
__device__ bf16 g_Wsct_hi[COUT*CIN],g_Wsct_lo[COUT*CIN];
__device__ bf16 g_kpwt_hi[D2*FKDIM],g_kpwt_lo[D2*FKDIM];
__device__ bf16 g_W2t_hi[COUT*D2],  g_W2t_lo[COUT*D2];

__device__ float g_sum1[D2],  g_sq1[D2],  g_scale1[D2],  g_shift1[D2];
__device__ float g_sumsc[COUT],g_sqsc[COUT],g_scalesc[COUT],g_shiftsc[COUT];
__device__ float g_sum2[COUT], g_sq2[COUT], g_scale2[COUT], g_shift2[COUT];

/* ------------------------- ptx helpers ---------------------------------- */
__device__ __forceinline__ void mma16816(float* c, const uint32_t* a, const uint32_t* b) {
    asm volatile("mma.sync.aligned.m16n8k16.row.col.f32.bf16.bf16.f32 "
        "{%0,%1,%2,%3}, {%4,%5,%6,%7}, {%8,%9}, {%0,%1,%2,%3};"
        : "+f"(c[0]), "+f"(c[1]), "+f"(c[2]), "+f"(c[3])
        : "r"(a[0]), "r"(a[1]), "r"(a[2]), "r"(a[3]), "r"(b[0]), "r"(b[1]));
}
__device__ __forceinline__ uint32_t ld32s(const bf16* p) {
    return *reinterpret_cast<const uint32_t*>(p);
}
__device__ __forceinline__ void cpasync16(void* s, const void* g) {
    uint32_t sa = (uint32_t)__cvta_generic_to_shared(s);
    asm volatile("cp.async.ca.shared.global [%0], [%1], 16;" :: "r"(sa), "l"(g) : "memory");
}
#define CP_COMMIT() asm volatile("cp.async.commit_group;" ::: "memory")
#define CP_WAIT1()  asm volatile("cp.async.wait_group 1;" ::: "memory")
#define CP_WAIT0()  asm volatile("cp.async.wait_group 0;" ::: "memory")

/* ------------------------- misc small kernels --------------------------- */
__global__ void k_zero() {
    int t = threadIdx.x;
    if (t < D2) { g_sum1[t] = 0.f; g_sq1[t] = 0.f; }
    g_sumsc[t] = 0.f; g_sqsc[t] = 0.f;
    g_sum2[t]  = 0.f; g_sq2[t]  = 0.f;
}

__device__ __forceinline__ void split_store(float v, bf16* hi, bf16* lo, size_t i) {
    bf16 h = __float2bfloat16(v);
    hi[i] = h;
    lo[i] = __float2bfloat16(v - __bfloat162float(h));
}

__global__ __launch_bounds__(256) void k_prep_feats(const float* __restrict__ f) {
    int i4 = blockIdx.x * 256 + threadIdx.x;            /* < 2,560,000 */
    float4 v = ((const float4*)f)[i4];
    bf16 h0 = __float2bfloat16(v.x), h1 = __float2bfloat16(v.y);
    bf16 h2 = __float2bfloat16(v.z), h3 = __float2bfloat16(v.w);
    union { bf16 b[4]; uint2 u; } H, L;
    H.b[0] = h0; H.b[1] = h1; H.b[2] = h2; H.b[3] = h3;
    L.b[0] = __float2bfloat16(v.x - __bfloat162float(h0));
    L.b[1] = __float2bfloat16(v.y - __bfloat162float(h1));
    L.b[2] = __float2bfloat16(v.z - __bfloat162float(h2));
    L.b[3] = __float2bfloat16(v.w - __bfloat162float(h3));
    ((uint2*)g_feats_hi)[i4] = H.u;
    ((uint2*)g_feats_lo)[i4] = L.u;
}

__global__ __launch_bounds__(256) void k_prep_w(const float* __restrict__ W1,
                                                const float* __restrict__ Wsc,
                                                const float* __restrict__ kpw,
                                                const float* __restrict__ W2)
{
    int i = blockIdx.x * 256 + threadIdx.x;             /* < 118784 */
    if (i < 8192) {                                     /* W1t [64,128] */
        int e = i >> 7, k = i & 127;
        split_store(W1[k * D2 + e], g_W1t_hi, g_W1t_lo, i);
    } else if (i < 40960) {                             /* Wsct [256,128] */
        int j = i - 8192; int e = j >> 7, k = j & 127;
        split_store(Wsc[k * COUT + e], g_Wsct_hi, g_Wsct_lo, j);
    } else if (i < 102400) {                            /* kpwt [64,960] */
        int j = i - 40960; int e = j / FKDIM, kd = j % FKDIM;
        split_store(kpw[(size_t)kd * D2 + e], g_kpwt_hi, g_kpwt_lo, j);
    } else {                                            /* W2t [256,64] */
        int j = i - 102400; int e = j >> 6, k = j & 63;
        split_store(W2[k * COUT + e], g_W2t_hi, g_W2t_lo, j);
    }
}

__device__ __forceinline__ void fin_one(int c, const float* sum, const float* sq,
                                        const float* g, const float* b,
                                        float* scale, float* shift)
{
    float m = sum[c] * (1.0f / NPTS);
    float v = sq[c] * (1.0f / NPTS) - m * m;
    float s = g[c] * rsqrtf(v + EPSBN);
    scale[c] = s;
    shift[c] = b[c] - m * s;
}
/* fused fin1 + finsc: 320 threads */
__global__ void k_fin1sc(const float* g1, const float* b1,
                         const float* gsc, const float* bsc)
{
    int t = threadIdx.x;
    if (t < D2) fin_one(t, g_sum1, g_sq1, g1, b1, g_scale1, g_shift1);
    else        fin_one(t - D2, g_sumsc, g_sqsc, gsc, bsc, g_scalesc, g_shiftsc);
}
__global__ void k_fin2(const float* g, const float* b) {
    fin_one(threadIdx.x, g_sum2, g_sq2, g, b, g_scale2, g_shift2);
}

/* ------------------------- HMMA split-bf16 GEMM + cp.async pipeline ------ */
/* Tile 128x64, 256 thr = 8 warps (4 m x 2 n), warp tile 32x32.
   VERIFIED fragment addressing + double-buffered cp.async + fused BN stats.
   n0 passed explicitly so one kernel can mix output targets.
   D = Ah*Bh + Ah*Bl + Al*Bh (fp32 accum).
   MODE 0: fp32 C + stats.  MODE 1: split bf16 hi/lo C (ld 64). */
#define AST 40
#define BUF_ELEMS 15360
#define OFF_AL 5120
#define OFF_BH 10240
#define OFF_BL 12800
#define GEMM_SMEM 61440

template<int KTOT, int MODE>
__device__ __forceinline__ void mmagemm_body(
    const bf16* __restrict__ Ahi, const bf16* __restrict__ Alo,
    const bf16* __restrict__ Bhi, const bf16* __restrict__ Blo,
    float* __restrict__ Cf, int ldc,
    bf16* __restrict__ Chi, bf16* __restrict__ Clo,
    float* __restrict__ sumP, float* __restrict__ sqP, int n0)
{
    extern __shared__ __align__(16) bf16 smem[];

    const int t = threadIdx.x, lane = t & 31, wid = t >> 5;
    const int wm = wid & 3, wn = wid >> 2;
    const int m0 = blockIdx.x * 128;
    const int gr = lane >> 2, gc2 = (lane & 3) * 2;

    const int arow0 = t >> 2, ac8 = (t & 3) * 8;
    const int brow = t >> 2,  bc8 = (t & 3) * 8;

    float acc[2][4][4];
#pragma unroll
    for (int i = 0; i < 2; i++)
#pragma unroll
        for (int j = 0; j < 4; j++)
#pragma unroll
            for (int q = 0; q < 4; q++) acc[i][j][q] = 0.f;

    constexpr int NCH = KTOT / 32;

    auto issue = [&](int kc) {
        bf16* buf = smem + (kc & 1) * BUF_ELEMS;
#pragma unroll
        for (int it = 0; it < 2; it++) {
            int row = arow0 + it * 64;
            size_t gsrc = (size_t)(m0 + row) * KTOT + kc * 32 + ac8;
            cpasync16(buf + row * AST + ac8, Ahi + gsrc);
            cpasync16(buf + OFF_AL + row * AST + ac8, Alo + gsrc);
        }
        {
            size_t gsrc = (size_t)(n0 + brow) * KTOT + kc * 32 + bc8;
            cpasync16(buf + OFF_BH + brow * AST + bc8, Bhi + gsrc);
            cpasync16(buf + OFF_BL + brow * AST + bc8, Blo + gsrc);
        }
        CP_COMMIT();
    };

    issue(0);

    for (int kc = 0; kc < NCH; kc++) {
        if (kc + 1 < NCH) { issue(kc + 1); CP_WAIT1(); }
        else              { CP_WAIT0(); }
        __syncthreads();

        const bf16* sAh = smem + (kc & 1) * BUF_ELEMS;
        const bf16* sAl = sAh + OFF_AL;
        const bf16* sBh = sAh + OFF_BH;
        const bf16* sBl = sAh + OFF_BL;

#pragma unroll
        for (int kk = 0; kk < 2; kk++) {
            const int kb = kk * 16;
            uint32_t ah[2][4], al[2][4], bh[4][2], bl[4][2];
#pragma unroll
            for (int mt = 0; mt < 2; mt++) {
                const bf16* ph = sAh + (wm * 32 + mt * 16 + gr) * AST + kb + gc2;
                ah[mt][0] = ld32s(ph);
                ah[mt][1] = ld32s(ph + 8 * AST);
                ah[mt][2] = ld32s(ph + 8);
                ah[mt][3] = ld32s(ph + 8 * AST + 8);
                const bf16* pl = sAl + (wm * 32 + mt * 16 + gr) * AST + kb + gc2;
                al[mt][0] = ld32s(pl);
                al[mt][1] = ld32s(pl + 8 * AST);
                al[mt][2] = ld32s(pl + 8);
                al[mt][3] = ld32s(pl + 8 * AST + 8);
            }
#pragma unroll
            for (int nt = 0; nt < 4; nt++) {
                const bf16* ph = sBh + (wn * 32 + nt * 8 + gr) * AST + kb + gc2;
                bh[nt][0] = ld32s(ph);
                bh[nt][1] = ld32s(ph + 8);
                const bf16* pl = sBl + (wn * 32 + nt * 8 + gr) * AST + kb + gc2;
                bl[nt][0] = ld32s(pl);
                bl[nt][1] = ld32s(pl + 8);
            }
#pragma unroll
            for (int mt = 0; mt < 2; mt++)
#pragma unroll
                for (int nt = 0; nt < 4; nt++) {
                    mma16816(acc[mt][nt], ah[mt], bh[nt]);
                    mma16816(acc[mt][nt], ah[mt], bl[nt]);
                    mma16816(acc[mt][nt], al[mt], bh[nt]);
                }
        }
        __syncthreads();
    }

    const int rbase = m0 + wm * 32 + gr;
    const int cbase = wn * 32 + gc2;

    if (MODE == 0) {
#pragma unroll
        for (int mt = 0; mt < 2; mt++)
#pragma unroll
            for (int nt = 0; nt < 4; nt++) {
                int r0 = rbase + mt * 16, r1 = r0 + 8;
                int cc = n0 + cbase + nt * 8;
                *(float2*)(Cf + (size_t)r0 * ldc + cc) =
                    make_float2(acc[mt][nt][0], acc[mt][nt][1]);
                *(float2*)(Cf + (size_t)r1 * ldc + cc) =
                    make_float2(acc[mt][nt][2], acc[mt][nt][3]);
            }

        float cs[8], cq[8];
#pragma unroll
        for (int nt = 0; nt < 4; nt++)
#pragma unroll
            for (int j = 0; j < 2; j++) {
                float v0 = acc[0][nt][j],     v1 = acc[0][nt][2 + j];
                float v2 = acc[1][nt][j],     v3 = acc[1][nt][2 + j];
                cs[nt * 2 + j] = v0 + v1 + v2 + v3;
                cq[nt * 2 + j] = v0 * v0 + v1 * v1 + v2 * v2 + v3 * v3;
            }
#pragma unroll
        for (int off = 4; off < 32; off <<= 1)
#pragma unroll
            for (int i = 0; i < 8; i++) {
                cs[i] += __shfl_xor_sync(0xffffffffu, cs[i], off);
                cq[i] += __shfl_xor_sync(0xffffffffu, cq[i], off);
            }

        float* fs = (float*)smem;
        if (t < 128) fs[t] = 0.f;
        __syncthreads();
        if ((lane & 28) == 0) {
#pragma unroll
            for (int nt = 0; nt < 4; nt++)
#pragma unroll
                for (int j = 0; j < 2; j++) {
                    int col = wn * 32 + (lane & 3) * 2 + nt * 8 + j;
                    atomicAdd(&fs[col],      cs[nt * 2 + j]);
                    atomicAdd(&fs[64 + col], cq[nt * 2 + j]);
                }
        }
        __syncthreads();
        if (t < 64) {
            atomicAdd(&sumP[n0 + t], fs[t]);
            atomicAdd(&sqP[n0 + t],  fs[64 + t]);
        }
    } else {
#pragma unroll
        for (int mt = 0; mt < 2; mt++)
#pragma unroll
            for (int nt = 0; nt < 4; nt++) {
                int cc = n0 + cbase + nt * 8;
#pragma unroll
                for (int half = 0; half < 2; half++) {
                    int rr = rbase + mt * 16 + half * 8;
                    float v0 = acc[mt][nt][half * 2 + 0];
                    float v1 = acc[mt][nt][half * 2 + 1];
                    union { bf16 b[2]; uint32_t u; } H, L;
                    bf16 h0 = __float2bfloat16(v0), h1 = __float2bfloat16(v1);
                    H.b[0] = h0; H.b[1] = h1;
                    L.b[0] = __float2bfloat16(v0 - __bfloat162float(h0));
                    L.b[1] = __float2bfloat16(v1 - __bfloat162float(h1));
                    *(uint32_t*)(Chi + (size_t)rr * 64 + cc) = H.u;
                    *(uint32_t*)(Clo + (size_t)rr * 64 + cc) = L.u;
                }
            }
    }
}

/* wrappers: globals bound in DEVICE code */
/* combined unary1 + shortcut: grid (625, 5). y==0 -> u1 tile, y>=1 -> sc. */
__global__ __launch_bounds__(256) void k_gemm_u1sc() {
    if (blockIdx.y == 0)
        mmagemm_body<128, 0>(g_feats_hi, g_feats_lo, g_W1t_hi, g_W1t_lo,
                             g_x1, D2, nullptr, nullptr, g_sum1, g_sq1, 0);
    else
        mmagemm_body<128, 0>(g_feats_hi, g_feats_lo, g_Wsct_hi, g_Wsct_lo,
                             g_sc, COUT, nullptr, nullptr, g_sumsc, g_sqsc,
                             (blockIdx.y - 1) * 64);
}
__global__ __launch_bounds__(256) void k_gemm_fk() {
    mmagemm_body<960, 1>(g_fk_hi, g_fk_lo, g_kpwt_hi, g_kpwt_lo,
                         nullptr, 0, g_xmid_hi, g_xmid_lo, nullptr, nullptr, 0);
}
__global__ __launch_bounds__(256) void k_gemm_u2(float* __restrict__ out) {
    mmagemm_body<64, 0>(g_xmid_hi, g_xmid_lo, g_W2t_hi, g_W2t_lo,
                        out, COUT, nullptr, nullptr, g_sum2, g_sq2,
                        blockIdx.y * 64);
}

/* ------------------------- KPConv (sparse influence) -------------------- */
__device__ __forceinline__ float fsqrt_approx(float x) {
    float r; asm("sqrt.approx.f32 %0, %1;" : "=f"(r) : "f"(x)); return r;
}

__global__ __launch_bounds__(256) void k_kpconv(const float* __restrict__ xyz,
                                                const int* __restrict__ nidx,
                                                const float* __restrict__ kp)
{
    __shared__ float kps[KPN][3];
    __shared__ float ws[8][NBH][KPN];
    const int t = threadIdx.x;
    if (t < KPN * 3) ((float*)kps)[t] = kp[t];
    __syncthreads();

    const int warp = t >> 5, lane = t & 31;
    const int n = blockIdx.x * 8 + warp;

    const float cx = xyz[n * 3 + 0], cy = xyz[n * 3 + 1], cz = xyz[n * 3 + 2];
    const int j = nidx[n * NBH + lane];
    const float rx = xyz[j * 3 + 0] - cx;
    const float ry = xyz[j * 3 + 1] - cy;
    const float rz = xyz[j * 3 + 2] - cz;

    unsigned mask = 0;
#pragma unroll
    for (int k = 0; k < KPN; k++) {
        float dx = rx - kps[k][0], dy = ry - kps[k][1], dz = rz - kps[k][2];
        float sq = dx * dx + dy * dy + dz * dz;
        float w = 1.0f - fsqrt_approx(sq) * INV_INFL;
        w = w > 0.f ? w : 0.f;
        ws[warp][lane][k] = w;
        if (w > 0.f) mask |= (1u << k);
    }
    __syncwarp();

    const float sc0 = g_scale1[2 * lane], sc1 = g_scale1[2 * lane + 1];
    const float sh0 = g_shift1[2 * lane], sh1 = g_shift1[2 * lane + 1];
    const float2* x1v = (const float2*)g_x1;

    float fk0[KPN], fk1[KPN];
#pragma unroll
    for (int k = 0; k < KPN; k++) { fk0[k] = 0.f; fk1[k] = 0.f; }

    for (int h = 0; h < NBH; h++) {
        unsigned mh = __shfl_sync(0xffffffffu, mask, h);
        if (!mh) continue;                                 /* warp-uniform */
        int jj = __shfl_sync(0xffffffffu, j, h);
        float2 v = x1v[(size_t)jj * 32 + lane];
        float a = v.x * sc0 + sh0; a = a > 0.f ? a : SLOPE * a;
        float b = v.y * sc1 + sh1; b = b > 0.f ? b : SLOPE * b;
        while (mh) {
            int k = __ffs(mh) - 1; mh &= mh - 1;
            float w = ws[warp][h][k];
            fk0[k] += w * a;
            fk1[k] += w * b;
        }
    }

    bf16* oh = g_fk_hi + (size_t)n * FKDIM;
    bf16* ol = g_fk_lo + (size_t)n * FKDIM;
#pragma unroll
    for (int k = 0; k < KPN; k++) {
        union { bf16 b[2]; uint32_t u; } H, L;
        bf16 h0 = __float2bfloat16(fk0[k]), h1 = __float2bfloat16(fk1[k]);
        H.b[0] = h0; H.b[1] = h1;
        L.b[0] = __float2bfloat16(fk0[k] - __bfloat162float(h0));
        L.b[1] = __float2bfloat16(fk1[k] - __bfloat162float(h1));
        *(uint32_t*)(oh + k * 64 + 2 * lane) = H.u;
        *(uint32_t*)(ol + k * 64 + 2 * lane) = L.u;
    }
}

/* ------------------------- final epilogue — known good ------------------- */
__global__ __launch_bounds__(256) void k_epilogue(float* __restrict__ out)
{
    __shared__ float s2[COUT], h2[COUT], ss[COUT], hs[COUT];
    const int t = threadIdx.x;
    s2[t] = g_scale2[t];  h2[t] = g_shift2[t];
    ss[t] = g_scalesc[t]; hs[t] = g_shiftsc[t];
    __syncthreads();

    const int idx = blockIdx.x * 256 + t;          /* float4 index */
    const int c4 = (idx & 63) * 4;

    float4 x = ((float4*)out)[idx];
    float4 s = ((const float4*)g_sc)[idx];
    float v0 = x.x * s2[c4 + 0] + h2[c4 + 0]; v0 = v0 > 0.f ? v0 : SLOPE * v0;
    float v1 = x.y * s2[c4 + 1] + h2[c4 + 1]; v1 = v1 > 0.f ? v1 : SLOPE * v1;
    float v2 = x.z * s2[c4 + 2] + h2[c4 + 2]; v2 = v2 > 0.f ? v2 : SLOPE * v2;
    float v3 = x.w * s2[c4 + 3] + h2[c4 + 3]; v3 = v3 > 0.f ? v3 : SLOPE * v3;
    float4 r;
    r.x = v0 + s.x * ss[c4 + 0] + hs[c4 + 0];
    r.y = v1 + s.y * ss[c4 + 1] + hs[c4 + 1];
    r.z = v2 + s.z * ss[c4 + 2] + hs[c4 + 2];
    r.w = v3 + s.w * ss[c4 + 3] + hs[c4 + 3];
    ((float4*)out)[idx] = r;
}

/* ------------------------- launch ---------------------------------------- */
extern "C" void kernel_launch(void* const* d_in, const int* in_sizes, int n_in,
                              void* d_out, int out_size)
{
    const float* feats = (const float*)d_in[0];
    const float* xyz   = (const float*)d_in[1];
    const int*   nidx  = (const int*)d_in[3];
    const float* W1    = (const float*)d_in[4];
    const float* g1    = (const float*)d_in[5];
    const float* b1    = (const float*)d_in[6];
    const float* kp    = (const float*)d_in[7];
    const float* kpw   = (const float*)d_in[8];
    const float* W2    = (const float*)d_in[9];
    const float* g2    = (const float*)d_in[10];
    const float* b2    = (const float*)d_in[11];
    const float* Wsc   = (const float*)d_in[12];
    const float* gsc   = (const float*)d_in[13];
    const float* bsc   = (const float*)d_in[14];
    float* out = (float*)d_out;

    static bool attr_done = false;
    if (!attr_done) {
        cudaFuncSetAttribute(k_gemm_u1sc, cudaFuncAttributeMaxDynamicSharedMemorySize, GEMM_SMEM);
        cudaFuncSetAttribute(k_gemm_fk,   cudaFuncAttributeMaxDynamicSharedMemorySize, GEMM_SMEM);
        cudaFuncSetAttribute(k_gemm_u2,   cudaFuncAttributeMaxDynamicSharedMemorySize, GEMM_SMEM);
        attr_done = true;
    }

    k_zero<<<1, 256>>>();
    k_prep_feats<<<(NPTS * CIN / 4) / 256, 256>>>(feats);
    k_prep_w<<<464, 256>>>(W1, Wsc, kpw, W2);

    /* unary1 + shortcut + both fused stats, one launch */
    k_gemm_u1sc<<<dim3(NPTS / 128, 5), 256, GEMM_SMEM>>>();

    k_fin1sc<<<1, D2 + COUT>>>(g1, b1, gsc, bsc);

    k_kpconv<<<NPTS / 8, 256>>>(xyz, nidx, kp);

    /* fk @ kpw -> xmid (bf16 split) */
    k_gemm_fk<<<dim3(NPTS / 128, 1), 256, GEMM_SMEM>>>();
    /* unary2 + fused stats2 */
    k_gemm_u2<<<dim3(NPTS / 128, 4), 256, GEMM_SMEM>>>(out);

    k_fin2<<<1, COUT>>>(g2, b2);

    k_epilogue<<<(NPTS * (COUT / 4)) / 256, 256>>>(out);
}

// round 13
// speedup vs baseline: 1.5449x; 1.0403x over previous
#include <cuda_runtime.h>
#include <cuda_bf16.h>
#include <cstdint>

#define NPTS 80000
#define NBH  32
#define KPN  15
#define CIN  128
#define D2   64
#define COUT 256
#define FKDIM (KPN*D2)   /* 960 */
#define INV_INFL 2.5f
#define EPSBN 1e-5f
#define SLOPE 0.2f

typedef __nv_bfloat16 bf16;

/* ------------------------- device scratch ------------------------------- */
/* Referenced ONLY from device code (host-side &__device__ = ATS trap). */
__device__ float g_x1[(size_t)NPTS*D2];
__device__ float g_sc[(size_t)NPTS*COUT];
__device__ bf16  g_feats_hi[(size_t)NPTS*CIN], g_feats_lo[(size_t)NPTS*CIN];
__device__ bf16  g_fk_hi[(size_t)NPTS*FKDIM], g_fk_lo[(size_t)NPTS*FKDIM];
__device__ bf16  g_xmid_hi[(size_t)NPTS*D2],  g_xmid_lo[(size_t)NPTS*D2];

__device__ bf16 g_W1t_hi[D2*CIN],   g_W1t_lo[D2*CIN];
__device__ bf16 g_Wsct_hi[COUT*CIN],g_Wsct_lo[COUT*CIN];
__device__ bf16 g_kpwt_hi[D2*FKDIM],g_kpwt_lo[D2*FKDIM];
__device__ bf16 g_W2t_hi[COUT*D2],  g_W2t_lo[COUT*D2];

__device__ float g_sum1[D2],  g_sq1[D2],  g_scale1[D2],  g_shift1[D2];
__device__ float g_sumsc[COUT],g_sqsc[COUT],g_scalesc[COUT],g_shiftsc[COUT];
__device__ float g_sum2[COUT], g_sq2[COUT], g_scale2[COUT], g_shift2[COUT];

/* ------------------------- ptx helpers ---------------------------------- */
__device__ __forceinline__ void mma16816(float* c, const uint32_t* a, const uint32_t* b) {
    asm volatile("mma.sync.aligned.m16n8k16.row.col.f32.bf16.bf16.f32 "
        "{%0,%1,%2,%3}, {%4,%5,%6,%7}, {%8,%9}, {%0,%1,%2,%3};"
        : "+f"(c[0]), "+f"(c[1]), "+f"(c[2]), "+f"(c[3])
        : "r"(a[0]), "r"(a[1]), "r"(a[2]), "r"(a[3]), "r"(b[0]), "r"(b[1]));
}
__device__ __forceinline__ void ldmx4(uint32_t& r0, uint32_t& r1, uint32_t& r2,
                                      uint32_t& r3, const bf16* p) {
    uint32_t a = (uint32_t)__cvta_generic_to_shared(p);
    asm volatile("ldmatrix.sync.aligned.m8n8.x4.shared.b16 {%0,%1,%2,%3}, [%4];"
        : "=r"(r0), "=r"(r1), "=r"(r2), "=r"(r3) : "r"(a));
}
__device__ __forceinline__ void cpasync16(void* s, const void* g) {
    uint32_t sa = (uint32_t)__cvta_generic_to_shared(s);
    asm volatile("cp.async.ca.shared.global [%0], [%1], 16;" :: "r"(sa), "l"(g) : "memory");
}
#define CP_COMMIT() asm volatile("cp.async.commit_group;" ::: "memory")
#define CP_WAIT1()  asm volatile("cp.async.wait_group 1;" ::: "memory")
#define CP_WAIT0()  asm volatile("cp.async.wait_group 0;" ::: "memory")

/* ------------------------- misc small kernels --------------------------- */
__global__ void k_zero() {
    int t = threadIdx.x;
    if (t < D2) { g_sum1[t] = 0.f; g_sq1[t] = 0.f; }
    g_sumsc[t] = 0.f; g_sqsc[t] = 0.f;
    g_sum2[t]  = 0.f; g_sq2[t]  = 0.f;
}

__device__ __forceinline__ void split_store(float v, bf16* hi, bf16* lo, size_t i) {
    bf16 h = __float2bfloat16(v);
    hi[i] = h;
    lo[i] = __float2bfloat16(v - __bfloat162float(h));
}

__global__ __launch_bounds__(256) void k_prep_feats(const float* __restrict__ f) {
    int i4 = blockIdx.x * 256 + threadIdx.x;            /* < 2,560,000 */
    float4 v = ((const float4*)f)[i4];
    bf16 h0 = __float2bfloat16(v.x), h1 = __float2bfloat16(v.y);
    bf16 h2 = __float2bfloat16(v.z), h3 = __float2bfloat16(v.w);
    union { bf16 b[4]; uint2 u; } H, L;
    H.b[0] = h0; H.b[1] = h1; H.b[2] = h2; H.b[3] = h3;
    L.b[0] = __float2bfloat16(v.x - __bfloat162float(h0));
    L.b[1] = __float2bfloat16(v.y - __bfloat162float(h1));
    L.b[2] = __float2bfloat16(v.z - __bfloat162float(h2));
    L.b[3] = __float2bfloat16(v.w - __bfloat162float(h3));
    ((uint2*)g_feats_hi)[i4] = H.u;
    ((uint2*)g_feats_lo)[i4] = L.u;
}

__global__ __launch_bounds__(256) void k_prep_w(const float* __restrict__ W1,
                                                const float* __restrict__ Wsc,
                                                const float* __restrict__ kpw,
                                                const float* __restrict__ W2)
{
    int i = blockIdx.x * 256 + threadIdx.x;             /* < 118784 */
    if (i < 8192) {                                     /* W1t [64,128] */
        int e = i >> 7, k = i & 127;
        split_store(W1[k * D2 + e], g_W1t_hi, g_W1t_lo, i);
    } else if (i < 40960) {                             /* Wsct [256,128] */
        int j = i - 8192; int e = j >> 7, k = j & 127;
        split_store(Wsc[k * COUT + e], g_Wsct_hi, g_Wsct_lo, j);
    } else if (i < 102400) {                            /* kpwt [64,960] */
        int j = i - 40960; int e = j / FKDIM, kd = j % FKDIM;
        split_store(kpw[(size_t)kd * D2 + e], g_kpwt_hi, g_kpwt_lo, j);
    } else {                                            /* W2t [256,64] */
        int j = i - 102400; int e = j >> 6, k = j & 63;
        split_store(W2[k * COUT + e], g_W2t_hi, g_W2t_lo, j);
    }
}

__device__ __forceinline__ void fin_one(int c, const float* sum, const float* sq,
                                        const float* g, const float* b,
                                        float* scale, float* shift)
{
    float m = sum[c] * (1.0f / NPTS);
    float v = sq[c] * (1.0f / NPTS) - m * m;
    float s = g[c] * rsqrtf(v + EPSBN);
    scale[c] = s;
    shift[c] = b[c] - m * s;
}
__global__ void k_fin1sc(const float* g1, const float* b1,
                         const float* gsc, const float* bsc)
{
    int t = threadIdx.x;
    if (t < D2) fin_one(t, g_sum1, g_sq1, g1, b1, g_scale1, g_shift1);
    else        fin_one(t - D2, g_sumsc, g_sqsc, gsc, bsc, g_scalesc, g_shiftsc);
}
__global__ void k_fin2(const float* g, const float* b) {
    fin_one(threadIdx.x, g_sum2, g_sq2, g, b, g_scale2, g_shift2);
}

/* ------------------------- HMMA split-bf16 GEMM + cp.async + ldmatrix ---- */
/* Tile 128x64, 256 thr = 8 warps (4 m x 2 n), warp tile 32x32.
   R13: fragment loads via ldmatrix.x4 (4x fewer shared-pipe instrs).
   A groups (m0-7/k0, m8-15/k0, m0-7/k8, m8-15/k8) and
   B groups (n0-7/k0, n0-7/k8, n8-15/k0, n8-15/k8) land in mma operand order.
   AST=40 elems (80 B): banks 20r mod 32 distinct per 8-row phase.
   D = Ah*Bh + Ah*Bl + Al*Bh (fp32 accum).
   MODE 0: fp32 C + fused stats.  MODE 1: split bf16 hi/lo C (ld 64). */
#define AST 40
#define BUF_ELEMS 15360
#define OFF_AL 5120
#define OFF_BH 10240
#define OFF_BL 12800
#define GEMM_SMEM 61440

template<int KTOT, int MODE>
__device__ __forceinline__ void mmagemm_body(
    const bf16* __restrict__ Ahi, const bf16* __restrict__ Alo,
    const bf16* __restrict__ Bhi, const bf16* __restrict__ Blo,
    float* __restrict__ Cf, int ldc,
    bf16* __restrict__ Chi, bf16* __restrict__ Clo,
    float* __restrict__ sumP, float* __restrict__ sqP, int n0)
{
    extern __shared__ __align__(16) bf16 smem[];

    const int t = threadIdx.x, lane = t & 31, wid = t >> 5;
    const int wm = wid & 3, wn = wid >> 2;
    const int m0 = blockIdx.x * 128;
    const int gr = lane >> 2, gc2 = (lane & 3) * 2;

    const int arow0 = t >> 2, ac8 = (t & 3) * 8;
    const int brow = t >> 2,  bc8 = (t & 3) * 8;

    /* ldmatrix per-lane source coords (element offsets) */
    const int rAf  = wm * 32 + (lane & 15);        /* + mt*16 */
    const int kA8  = (lane >> 4) * 8;              /* k-half select, elems */
    const int rBf  = wn * 32 + (lane & 7) + ((lane & 16) ? 8 : 0); /* + p*16 */
    const int kB8  = ((lane >> 3) & 1) * 8;

    float acc[2][4][4];
#pragma unroll
    for (int i = 0; i < 2; i++)
#pragma unroll
        for (int j = 0; j < 4; j++)
#pragma unroll
            for (int q = 0; q < 4; q++) acc[i][j][q] = 0.f;

    constexpr int NCH = KTOT / 32;

    auto issue = [&](int kc) {
        bf16* buf = smem + (kc & 1) * BUF_ELEMS;
#pragma unroll
        for (int it = 0; it < 2; it++) {
            int row = arow0 + it * 64;
            size_t gsrc = (size_t)(m0 + row) * KTOT + kc * 32 + ac8;
            cpasync16(buf + row * AST + ac8, Ahi + gsrc);
            cpasync16(buf + OFF_AL + row * AST + ac8, Alo + gsrc);
        }
        {
            size_t gsrc = (size_t)(n0 + brow) * KTOT + kc * 32 + bc8;
            cpasync16(buf + OFF_BH + brow * AST + bc8, Bhi + gsrc);
            cpasync16(buf + OFF_BL + brow * AST + bc8, Blo + gsrc);
        }
        CP_COMMIT();
    };

    issue(0);

    for (int kc = 0; kc < NCH; kc++) {
        if (kc + 1 < NCH) { issue(kc + 1); CP_WAIT1(); }
        else              { CP_WAIT0(); }
        __syncthreads();

        const bf16* sAh = smem + (kc & 1) * BUF_ELEMS;
        const bf16* sAl = sAh + OFF_AL;
        const bf16* sBh = sAh + OFF_BH;
        const bf16* sBl = sAh + OFF_BL;

#pragma unroll
        for (int kk = 0; kk < 2; kk++) {
            const int ke = kk * 16;
            uint32_t ah[2][4], al[2][4], bh[4][2], bl[4][2];
#pragma unroll
            for (int mt = 0; mt < 2; mt++) {
                const bf16* ph = sAh + (rAf + mt * 16) * AST + ke + kA8;
                ldmx4(ah[mt][0], ah[mt][1], ah[mt][2], ah[mt][3], ph);
                const bf16* pl = sAl + (rAf + mt * 16) * AST + ke + kA8;
                ldmx4(al[mt][0], al[mt][1], al[mt][2], al[mt][3], pl);
            }
#pragma unroll
            for (int p = 0; p < 2; p++) {
                const bf16* ph = sBh + (rBf + p * 16) * AST + ke + kB8;
                ldmx4(bh[2*p][0], bh[2*p][1], bh[2*p+1][0], bh[2*p+1][1], ph);
                const bf16* pl = sBl + (rBf + p * 16) * AST + ke + kB8;
                ldmx4(bl[2*p][0], bl[2*p][1], bl[2*p+1][0], bl[2*p+1][1], pl);
            }
#pragma unroll
            for (int mt = 0; mt < 2; mt++)
#pragma unroll
                for (int nt = 0; nt < 4; nt++) {
                    mma16816(acc[mt][nt], ah[mt], bh[nt]);
                    mma16816(acc[mt][nt], ah[mt], bl[nt]);
                    mma16816(acc[mt][nt], al[mt], bh[nt]);
                }
        }
        __syncthreads();
    }

    const int rbase = m0 + wm * 32 + gr;
    const int cbase = wn * 32 + gc2;

    if (MODE == 0) {
#pragma unroll
        for (int mt = 0; mt < 2; mt++)
#pragma unroll
            for (int nt = 0; nt < 4; nt++) {
                int r0 = rbase + mt * 16, r1 = r0 + 8;
                int cc = n0 + cbase + nt * 8;
                *(float2*)(Cf + (size_t)r0 * ldc + cc) =
                    make_float2(acc[mt][nt][0], acc[mt][nt][1]);
                *(float2*)(Cf + (size_t)r1 * ldc + cc) =
                    make_float2(acc[mt][nt][2], acc[mt][nt][3]);
            }

        float cs[8], cq[8];
#pragma unroll
        for (int nt = 0; nt < 4; nt++)
#pragma unroll
            for (int j = 0; j < 2; j++) {
                float v0 = acc[0][nt][j],     v1 = acc[0][nt][2 + j];
                float v2 = acc[1][nt][j],     v3 = acc[1][nt][2 + j];
                cs[nt * 2 + j] = v0 + v1 + v2 + v3;
                cq[nt * 2 + j] = v0 * v0 + v1 * v1 + v2 * v2 + v3 * v3;
            }
#pragma unroll
        for (int off = 4; off < 32; off <<= 1)
#pragma unroll
            for (int i = 0; i < 8; i++) {
                cs[i] += __shfl_xor_sync(0xffffffffu, cs[i], off);
                cq[i] += __shfl_xor_sync(0xffffffffu, cq[i], off);
            }

        float* fs = (float*)smem;
        if (t < 128) fs[t] = 0.f;
        __syncthreads();
        if ((lane & 28) == 0) {
#pragma unroll
            for (int nt = 0; nt < 4; nt++)
#pragma unroll
                for (int j = 0; j < 2; j++) {
                    int col = wn * 32 + (lane & 3) * 2 + nt * 8 + j;
                    atomicAdd(&fs[col],      cs[nt * 2 + j]);
                    atomicAdd(&fs[64 + col], cq[nt * 2 + j]);
                }
        }
        __syncthreads();
        if (t < 64) {
            atomicAdd(&sumP[n0 + t], fs[t]);
            atomicAdd(&sqP[n0 + t],  fs[64 + t]);
        }
    } else {
#pragma unroll
        for (int mt = 0; mt < 2; mt++)
#pragma unroll
            for (int nt = 0; nt < 4; nt++) {
                int cc = n0 + cbase + nt * 8;
#pragma unroll
                for (int half = 0; half < 2; half++) {
                    int rr = rbase + mt * 16 + half * 8;
                    float v0 = acc[mt][nt][half * 2 + 0];
                    float v1 = acc[mt][nt][half * 2 + 1];
                    union { bf16 b[2]; uint32_t u; } H, L;
                    bf16 h0 = __float2bfloat16(v0), h1 = __float2bfloat16(v1);
                    H.b[0] = h0; H.b[1] = h1;
                    L.b[0] = __float2bfloat16(v0 - __bfloat162float(h0));
                    L.b[1] = __float2bfloat16(v1 - __bfloat162float(h1));
                    *(uint32_t*)(Chi + (size_t)rr * 64 + cc) = H.u;
                    *(uint32_t*)(Clo + (size_t)rr * 64 + cc) = L.u;
                }
            }
    }
}

/* wrappers: globals bound in DEVICE code */
__global__ __launch_bounds__(256) void k_gemm_u1sc() {
    if (blockIdx.y == 0)
        mmagemm_body<128, 0>(g_feats_hi, g_feats_lo, g_W1t_hi, g_W1t_lo,
                             g_x1, D2, nullptr, nullptr, g_sum1, g_sq1, 0);
    else
        mmagemm_body<128, 0>(g_feats_hi, g_feats_lo, g_Wsct_hi, g_Wsct_lo,
                             g_sc, COUT, nullptr, nullptr, g_sumsc, g_sqsc,
                             (blockIdx.y - 1) * 64);
}
__global__ __launch_bounds__(256) void k_gemm_fk() {
    mmagemm_body<960, 1>(g_fk_hi, g_fk_lo, g_kpwt_hi, g_kpwt_lo,
                         nullptr, 0, g_xmid_hi, g_xmid_lo, nullptr, nullptr, 0);
}
__global__ __launch_bounds__(256) void k_gemm_u2(float* __restrict__ out) {
    mmagemm_body<64, 0>(g_xmid_hi, g_xmid_lo, g_W2t_hi, g_W2t_lo,
                        out, COUT, nullptr, nullptr, g_sum2, g_sq2,
                        blockIdx.y * 64);
}

/* ------------------------- KPConv (sparse influence) -------------------- */
__device__ __forceinline__ float fsqrt_approx(float x) {
    float r; asm("sqrt.approx.f32 %0, %1;" : "=f"(r) : "f"(x)); return r;
}

__global__ __launch_bounds__(256) void k_kpconv(const float* __restrict__ xyz,
                                                const int* __restrict__ nidx,
                                                const float* __restrict__ kp)
{
    __shared__ float kps[KPN][3];
    __shared__ float ws[8][NBH][KPN];
    const int t = threadIdx.x;
    if (t < KPN * 3) ((float*)kps)[t] = kp[t];
    __syncthreads();

    const int warp = t >> 5, lane = t & 31;
    const int n = blockIdx.x * 8 + warp;

    const float cx = xyz[n * 3 + 0], cy = xyz[n * 3 + 1], cz = xyz[n * 3 + 2];
    const int j = nidx[n * NBH + lane];
    const float rx = xyz[j * 3 + 0] - cx;
    const float ry = xyz[j * 3 + 1] - cy;
    const float rz = xyz[j * 3 + 2] - cz;

    unsigned mask = 0;
#pragma unroll
    for (int k = 0; k < KPN; k++) {
        float dx = rx - kps[k][0], dy = ry - kps[k][1], dz = rz - kps[k][2];
        float sq = dx * dx + dy * dy + dz * dz;
        float w = 1.0f - fsqrt_approx(sq) * INV_INFL;
        w = w > 0.f ? w : 0.f;
        ws[warp][lane][k] = w;
        if (w > 0.f) mask |= (1u << k);
    }
    __syncwarp();

    const float sc0 = g_scale1[2 * lane], sc1 = g_scale1[2 * lane + 1];
    const float sh0 = g_shift1[2 * lane], sh1 = g_shift1[2 * lane + 1];
    const float2* x1v = (const float2*)g_x1;

    float fk0[KPN], fk1[KPN];
#pragma unroll
    for (int k = 0; k < KPN; k++) { fk0[k] = 0.f; fk1[k] = 0.f; }

    for (int h = 0; h < NBH; h++) {
        unsigned mh = __shfl_sync(0xffffffffu, mask, h);
        if (!mh) continue;                                 /* warp-uniform */
        int jj = __shfl_sync(0xffffffffu, j, h);
        float2 v = x1v[(size_t)jj * 32 + lane];
        float a = v.x * sc0 + sh0; a = a > 0.f ? a : SLOPE * a;
        float b = v.y * sc1 + sh1; b = b > 0.f ? b : SLOPE * b;
        while (mh) {
            int k = __ffs(mh) - 1; mh &= mh - 1;
            float w = ws[warp][h][k];
            fk0[k] += w * a;
            fk1[k] += w * b;
        }
    }

    bf16* oh = g_fk_hi + (size_t)n * FKDIM;
    bf16* ol = g_fk_lo + (size_t)n * FKDIM;
#pragma unroll
    for (int k = 0; k < KPN; k++) {
        union { bf16 b[2]; uint32_t u; } H, L;
        bf16 h0 = __float2bfloat16(fk0[k]), h1 = __float2bfloat16(fk1[k]);
        H.b[0] = h0; H.b[1] = h1;
        L.b[0] = __float2bfloat16(fk0[k] - __bfloat162float(h0));
        L.b[1] = __float2bfloat16(fk1[k] - __bfloat162float(h1));
        *(uint32_t*)(oh + k * 64 + 2 * lane) = H.u;
        *(uint32_t*)(ol + k * 64 + 2 * lane) = L.u;
    }
}

/* ------------------------- final epilogue — known good ------------------- */
__global__ __launch_bounds__(256) void k_epilogue(float* __restrict__ out)
{
    __shared__ float s2[COUT], h2[COUT], ss[COUT], hs[COUT];
    const int t = threadIdx.x;
    s2[t] = g_scale2[t];  h2[t] = g_shift2[t];
    ss[t] = g_scalesc[t]; hs[t] = g_shiftsc[t];
    __syncthreads();

    const int idx = blockIdx.x * 256 + t;          /* float4 index */
    const int c4 = (idx & 63) * 4;

    float4 x = ((float4*)out)[idx];
    float4 s = ((const float4*)g_sc)[idx];
    float v0 = x.x * s2[c4 + 0] + h2[c4 + 0]; v0 = v0 > 0.f ? v0 : SLOPE * v0;
    float v1 = x.y * s2[c4 + 1] + h2[c4 + 1]; v1 = v1 > 0.f ? v1 : SLOPE * v1;
    float v2 = x.z * s2[c4 + 2] + h2[c4 + 2]; v2 = v2 > 0.f ? v2 : SLOPE * v2;
    float v3 = x.w * s2[c4 + 3] + h2[c4 + 3]; v3 = v3 > 0.f ? v3 : SLOPE * v3;
    float4 r;
    r.x = v0 + s.x * ss[c4 + 0] + hs[c4 + 0];
    r.y = v1 + s.y * ss[c4 + 1] + hs[c4 + 1];
    r.z = v2 + s.z * ss[c4 + 2] + hs[c4 + 2];
    r.w = v3 + s.w * ss[c4 + 3] + hs[c4 + 3];
    ((float4*)out)[idx] = r;
}

/* ------------------------- launch ---------------------------------------- */
extern "C" void kernel_launch(void* const* d_in, const int* in_sizes, int n_in,
                              void* d_out, int out_size)
{
    const float* feats = (const float*)d_in[0];
    const float* xyz   = (const float*)d_in[1];
    const int*   nidx  = (const int*)d_in[3];
    const float* W1    = (const float*)d_in[4];
    const float* g1    = (const float*)d_in[5];
    const float* b1    = (const float*)d_in[6];
    const float* kp    = (const float*)d_in[7];
    const float* kpw   = (const float*)d_in[8];
    const float* W2    = (const float*)d_in[9];
    const float* g2    = (const float*)d_in[10];
    const float* b2    = (const float*)d_in[11];
    const float* Wsc   = (const float*)d_in[12];
    const float* gsc   = (const float*)d_in[13];
    const float* bsc   = (const float*)d_in[14];
    float* out = (float*)d_out;

    static bool attr_done = false;
    if (!attr_done) {
        cudaFuncSetAttribute(k_gemm_u1sc, cudaFuncAttributeMaxDynamicSharedMemorySize, GEMM_SMEM);
        cudaFuncSetAttribute(k_gemm_fk,   cudaFuncAttributeMaxDynamicSharedMemorySize, GEMM_SMEM);
        cudaFuncSetAttribute(k_gemm_u2,   cudaFuncAttributeMaxDynamicSharedMemorySize, GEMM_SMEM);
        attr_done = true;
    }

    k_zero<<<1, 256>>>();
    k_prep_feats<<<(NPTS * CIN / 4) / 256, 256>>>(feats);
    k_prep_w<<<464, 256>>>(W1, Wsc, kpw, W2);

    /* unary1 + shortcut + both fused stats, one launch */
    k_gemm_u1sc<<<dim3(NPTS / 128, 5), 256, GEMM_SMEM>>>();

    k_fin1sc<<<1, D2 + COUT>>>(g1, b1, gsc, bsc);

    k_kpconv<<<NPTS / 8, 256>>>(xyz, nidx, kp);

    /* fk @ kpw -> xmid (bf16 split) */
    k_gemm_fk<<<dim3(NPTS / 128, 1), 256, GEMM_SMEM>>>();
    /* unary2 + fused stats2 */
    k_gemm_u2<<<dim3(NPTS / 128, 4), 256, GEMM_SMEM>>>(out);

    k_fin2<<<1, COUT>>>(g2, b2);

    k_epilogue<<<(NPTS * (COUT / 4)) / 256, 256>>>(out);
}

// round 14
// speedup vs baseline: 1.5530x; 1.0052x over previous
#include <cuda_runtime.h>
#include <cuda_bf16.h>
#include <cstdint>

#define NPTS 80000
#define NBH  32
#define KPN  15
#define CIN  128
#define D2   64
#define COUT 256
#define FKDIM (KPN*D2)   /* 960 */
#define INV_INFL 2.5f
#define EPSBN 1e-5f
#define SLOPE 0.2f

typedef __nv_bfloat16 bf16;

/* ------------------------- device scratch ------------------------------- */
/* Referenced ONLY from device code (host-side &__device__ = ATS trap). */
__device__ float g_x1[(size_t)NPTS*D2];
__device__ float g_sc[(size_t)NPTS*COUT];
__device__ bf16  g_feats_hi[(size_t)NPTS*CIN], g_feats_lo[(size_t)NPTS*CIN];
__device__ bf16  g_fk_hi[(size_t)NPTS*FKDIM], g_fk_lo[(size_t)NPTS*FKDIM];
__device__ bf16  g_xmid_hi[(size_t)NPTS*D2],  g_xmid_lo[(size_t)NPTS*D2];

__device__ bf16 g_W1t_hi[D2*CIN],   g_W1t_lo[D2*CIN];
__device__ bf16 g_Wsct_hi[COUT*CIN],g_Wsct_lo[COUT*CIN];
__device__ bf16 g_kpwt_hi[D2*FKDIM],g_kpwt_lo[D2*FKDIM];
__device__ bf16 g_W2t_hi[COUT*D2],  g_W2t_lo[COUT*D2];

__device__ float g_sum1[D2],  g_sq1[D2];
__device__ float g_sumsc[COUT],g_sqsc[COUT];
__device__ float g_sum2[COUT], g_sq2[COUT];

/* ------------------------- ptx helpers ---------------------------------- */
__device__ __forceinline__ void mma16816(float* c, const uint32_t* a, const uint32_t* b) {
    asm volatile("mma.sync.aligned.m16n8k16.row.col.f32.bf16.bf16.f32 "
        "{%0,%1,%2,%3}, {%4,%5,%6,%7}, {%8,%9}, {%0,%1,%2,%3};"
        : "+f"(c[0]), "+f"(c[1]), "+f"(c[2]), "+f"(c[3])
        : "r"(a[0]), "r"(a[1]), "r"(a[2]), "r"(a[3]), "r"(b[0]), "r"(b[1]));
}
__device__ __forceinline__ void ldmx4(uint32_t& r0, uint32_t& r1, uint32_t& r2,
                                      uint32_t& r3, const bf16* p) {
    uint32_t a = (uint32_t)__cvta_generic_to_shared(p);
    asm volatile("ldmatrix.sync.aligned.m8n8.x4.shared.b16 {%0,%1,%2,%3}, [%4];"
        : "=r"(r0), "=r"(r1), "=r"(r2), "=r"(r3) : "r"(a));
}
__device__ __forceinline__ void cpasync16(void* s, const void* g) {
    uint32_t sa = (uint32_t)__cvta_generic_to_shared(s);
    asm volatile("cp.async.ca.shared.global [%0], [%1], 16;" :: "r"(sa), "l"(g) : "memory");
}
#define CP_COMMIT() asm volatile("cp.async.commit_group;" ::: "memory")
#define CP_WAIT1()  asm volatile("cp.async.wait_group 1;" ::: "memory")
#define CP_WAIT0()  asm volatile("cp.async.wait_group 0;" ::: "memory")

/* ------------------------- merged prep kernel --------------------------- */
__device__ __forceinline__ void split_store(float v, bf16* hi, bf16* lo, size_t i) {
    bf16 h = __float2bfloat16(v);
    hi[i] = h;
    lo[i] = __float2bfloat16(v - __bfloat162float(h));
}

/* grid = 10465: [0,10000) feats, [10000,10464) weights, 10464 zero-stats */
__global__ __launch_bounds__(256) void k_prep(const float* __restrict__ f,
                                              const float* __restrict__ W1,
                                              const float* __restrict__ Wsc,
                                              const float* __restrict__ kpw,
                                              const float* __restrict__ W2)
{
    const int b = blockIdx.x, t = threadIdx.x;
    if (b < 10000) {
        int i4 = b * 256 + t;                           /* < 2,560,000 */
        float4 v = ((const float4*)f)[i4];
        bf16 h0 = __float2bfloat16(v.x), h1 = __float2bfloat16(v.y);
        bf16 h2 = __float2bfloat16(v.z), h3 = __float2bfloat16(v.w);
        union { bf16 b_[4]; uint2 u; } H, L;
        H.b_[0] = h0; H.b_[1] = h1; H.b_[2] = h2; H.b_[3] = h3;
        L.b_[0] = __float2bfloat16(v.x - __bfloat162float(h0));
        L.b_[1] = __float2bfloat16(v.y - __bfloat162float(h1));
        L.b_[2] = __float2bfloat16(v.z - __bfloat162float(h2));
        L.b_[3] = __float2bfloat16(v.w - __bfloat162float(h3));
        ((uint2*)g_feats_hi)[i4] = H.u;
        ((uint2*)g_feats_lo)[i4] = L.u;
    } else if (b < 10464) {
        int i = (b - 10000) * 256 + t;                  /* < 118784 */
        if (i < 8192) {                                 /* W1t [64,128] */
            int e = i >> 7, k = i & 127;
            split_store(W1[k * D2 + e], g_W1t_hi, g_W1t_lo, i);
        } else if (i < 40960) {                         /* Wsct [256,128] */
            int j = i - 8192; int e = j >> 7, k = j & 127;
            split_store(Wsc[k * COUT + e], g_Wsct_hi, g_Wsct_lo, j);
        } else if (i < 102400) {                        /* kpwt [64,960] */
            int j = i - 40960; int e = j / FKDIM, kd = j % FKDIM;
            split_store(kpw[(size_t)kd * D2 + e], g_kpwt_hi, g_kpwt_lo, j);
        } else {                                        /* W2t [256,64] */
            int j = i - 102400; int e = j >> 6, k = j & 63;
            split_store(W2[k * COUT + e], g_W2t_hi, g_W2t_lo, j);
        }
    } else {
        if (t < D2) { g_sum1[t] = 0.f; g_sq1[t] = 0.f; }
        g_sumsc[t] = 0.f; g_sqsc[t] = 0.f;
        g_sum2[t]  = 0.f; g_sq2[t]  = 0.f;
    }
}

/* inline BN finalize from sums */
__device__ __forceinline__ void fin_calc(float sum, float sq, float g, float b,
                                         float& scale, float& shift)
{
    float m = sum * (1.0f / NPTS);
    float v = sq * (1.0f / NPTS) - m * m;
    float s = g * rsqrtf(v + EPSBN);
    scale = s;
    shift = b - m * s;
}

/* ------------------------- HMMA split-bf16 GEMM + cp.async + ldmatrix ---- */
#define AST 40
#define BUF_ELEMS 15360
#define OFF_AL 5120
#define OFF_BH 10240
#define OFF_BL 12800
#define GEMM_SMEM 61440

template<int KTOT, int MODE>
__device__ __forceinline__ void mmagemm_body(
    const bf16* __restrict__ Ahi, const bf16* __restrict__ Alo,
    const bf16* __restrict__ Bhi, const bf16* __restrict__ Blo,
    float* __restrict__ Cf, int ldc,
    bf16* __restrict__ Chi, bf16* __restrict__ Clo,
    float* __restrict__ sumP, float* __restrict__ sqP, int n0)
{
    extern __shared__ __align__(16) bf16 smem[];

    const int t = threadIdx.x, lane = t & 31, wid = t >> 5;
    const int wm = wid & 3, wn = wid >> 2;
    const int m0 = blockIdx.x * 128;
    const int gr = lane >> 2, gc2 = (lane & 3) * 2;

    const int arow0 = t >> 2, ac8 = (t & 3) * 8;
    const int brow = t >> 2,  bc8 = (t & 3) * 8;

    const int rAf  = wm * 32 + (lane & 15);
    const int kA8  = (lane >> 4) * 8;
    const int rBf  = wn * 32 + (lane & 7) + ((lane & 16) ? 8 : 0);
    const int kB8  = ((lane >> 3) & 1) * 8;

    float acc[2][4][4];
#pragma unroll
    for (int i = 0; i < 2; i++)
#pragma unroll
        for (int j = 0; j < 4; j++)
#pragma unroll
            for (int q = 0; q < 4; q++) acc[i][j][q] = 0.f;

    constexpr int NCH = KTOT / 32;

    auto issue = [&](int kc) {
        bf16* buf = smem + (kc & 1) * BUF_ELEMS;
#pragma unroll
        for (int it = 0; it < 2; it++) {
            int row = arow0 + it * 64;
            size_t gsrc = (size_t)(m0 + row) * KTOT + kc * 32 + ac8;
            cpasync16(buf + row * AST + ac8, Ahi + gsrc);
            cpasync16(buf + OFF_AL + row * AST + ac8, Alo + gsrc);
        }
        {
            size_t gsrc = (size_t)(n0 + brow) * KTOT + kc * 32 + bc8;
            cpasync16(buf + OFF_BH + brow * AST + bc8, Bhi + gsrc);
            cpasync16(buf + OFF_BL + brow * AST + bc8, Blo + gsrc);
        }
        CP_COMMIT();
    };

    issue(0);

    for (int kc = 0; kc < NCH; kc++) {
        if (kc + 1 < NCH) { issue(kc + 1); CP_WAIT1(); }
        else              { CP_WAIT0(); }
        __syncthreads();

        const bf16* sAh = smem + (kc & 1) * BUF_ELEMS;
        const bf16* sAl = sAh + OFF_AL;
        const bf16* sBh = sAh + OFF_BH;
        const bf16* sBl = sAh + OFF_BL;

#pragma unroll
        for (int kk = 0; kk < 2; kk++) {
            const int ke = kk * 16;
            uint32_t ah[2][4], al[2][4], bh[4][2], bl[4][2];
#pragma unroll
            for (int mt = 0; mt < 2; mt++) {
                const bf16* ph = sAh + (rAf + mt * 16) * AST + ke + kA8;
                ldmx4(ah[mt][0], ah[mt][1], ah[mt][2], ah[mt][3], ph);
                const bf16* pl = sAl + (rAf + mt * 16) * AST + ke + kA8;
                ldmx4(al[mt][0], al[mt][1], al[mt][2], al[mt][3], pl);
            }
#pragma unroll
            for (int p = 0; p < 2; p++) {
                const bf16* ph = sBh + (rBf + p * 16) * AST + ke + kB8;
                ldmx4(bh[2*p][0], bh[2*p][1], bh[2*p+1][0], bh[2*p+1][1], ph);
                const bf16* pl = sBl + (rBf + p * 16) * AST + ke + kB8;
                ldmx4(bl[2*p][0], bl[2*p][1], bl[2*p+1][0], bl[2*p+1][1], pl);
            }
#pragma unroll
            for (int mt = 0; mt < 2; mt++)
#pragma unroll
                for (int nt = 0; nt < 4; nt++) {
                    mma16816(acc[mt][nt], ah[mt], bh[nt]);
                    mma16816(acc[mt][nt], ah[mt], bl[nt]);
                    mma16816(acc[mt][nt], al[mt], bh[nt]);
                }
        }
        __syncthreads();
    }

    const int rbase = m0 + wm * 32 + gr;
    const int cbase = wn * 32 + gc2;

    if (MODE == 0) {
#pragma unroll
        for (int mt = 0; mt < 2; mt++)
#pragma unroll
            for (int nt = 0; nt < 4; nt++) {
                int r0 = rbase + mt * 16, r1 = r0 + 8;
                int cc = n0 + cbase + nt * 8;
                *(float2*)(Cf + (size_t)r0 * ldc + cc) =
                    make_float2(acc[mt][nt][0], acc[mt][nt][1]);
                *(float2*)(Cf + (size_t)r1 * ldc + cc) =
                    make_float2(acc[mt][nt][2], acc[mt][nt][3]);
            }

        float cs[8], cq[8];
#pragma unroll
        for (int nt = 0; nt < 4; nt++)
#pragma unroll
            for (int j = 0; j < 2; j++) {
                float v0 = acc[0][nt][j],     v1 = acc[0][nt][2 + j];
                float v2 = acc[1][nt][j],     v3 = acc[1][nt][2 + j];
                cs[nt * 2 + j] = v0 + v1 + v2 + v3;
                cq[nt * 2 + j] = v0 * v0 + v1 * v1 + v2 * v2 + v3 * v3;
            }
#pragma unroll
        for (int off = 4; off < 32; off <<= 1)
#pragma unroll
            for (int i = 0; i < 8; i++) {
                cs[i] += __shfl_xor_sync(0xffffffffu, cs[i], off);
                cq[i] += __shfl_xor_sync(0xffffffffu, cq[i], off);
            }

        float* fs = (float*)smem;
        if (t < 128) fs[t] = 0.f;
        __syncthreads();
        if ((lane & 28) == 0) {
#pragma unroll
            for (int nt = 0; nt < 4; nt++)
#pragma unroll
                for (int j = 0; j < 2; j++) {
                    int col = wn * 32 + (lane & 3) * 2 + nt * 8 + j;
                    atomicAdd(&fs[col],      cs[nt * 2 + j]);
                    atomicAdd(&fs[64 + col], cq[nt * 2 + j]);
                }
        }
        __syncthreads();
        if (t < 64) {
            atomicAdd(&sumP[n0 + t], fs[t]);
            atomicAdd(&sqP[n0 + t],  fs[64 + t]);
        }
    } else {
#pragma unroll
        for (int mt = 0; mt < 2; mt++)
#pragma unroll
            for (int nt = 0; nt < 4; nt++) {
                int cc = n0 + cbase + nt * 8;
#pragma unroll
                for (int half = 0; half < 2; half++) {
                    int rr = rbase + mt * 16 + half * 8;
                    float v0 = acc[mt][nt][half * 2 + 0];
                    float v1 = acc[mt][nt][half * 2 + 1];
                    union { bf16 b[2]; uint32_t u; } H, L;
                    bf16 h0 = __float2bfloat16(v0), h1 = __float2bfloat16(v1);
                    H.b[0] = h0; H.b[1] = h1;
                    L.b[0] = __float2bfloat16(v0 - __bfloat162float(h0));
                    L.b[1] = __float2bfloat16(v1 - __bfloat162float(h1));
                    *(uint32_t*)(Chi + (size_t)rr * 64 + cc) = H.u;
                    *(uint32_t*)(Clo + (size_t)rr * 64 + cc) = L.u;
                }
            }
    }
}

/* wrappers: globals bound in DEVICE code */
__global__ __launch_bounds__(256) void k_gemm_u1sc() {
    if (blockIdx.y == 0)
        mmagemm_body<128, 0>(g_feats_hi, g_feats_lo, g_W1t_hi, g_W1t_lo,
                             g_x1, D2, nullptr, nullptr, g_sum1, g_sq1, 0);
    else
        mmagemm_body<128, 0>(g_feats_hi, g_feats_lo, g_Wsct_hi, g_Wsct_lo,
                             g_sc, COUT, nullptr, nullptr, g_sumsc, g_sqsc,
                             (blockIdx.y - 1) * 64);
}
__global__ __launch_bounds__(256) void k_gemm_fk() {
    mmagemm_body<960, 1>(g_fk_hi, g_fk_lo, g_kpwt_hi, g_kpwt_lo,
                         nullptr, 0, g_xmid_hi, g_xmid_lo, nullptr, nullptr, 0);
}
__global__ __launch_bounds__(256) void k_gemm_u2(float* __restrict__ out) {
    mmagemm_body<64, 0>(g_xmid_hi, g_xmid_lo, g_W2t_hi, g_W2t_lo,
                        out, COUT, nullptr, nullptr, g_sum2, g_sq2,
                        blockIdx.y * 64);
}

/* ------------------------- KPConv (sparse influence, inline fin1) -------- */
__device__ __forceinline__ float fsqrt_approx(float x) {
    float r; asm("sqrt.approx.f32 %0, %1;" : "=f"(r) : "f"(x)); return r;
}

__global__ __launch_bounds__(256) void k_kpconv(const float* __restrict__ xyz,
                                                const int* __restrict__ nidx,
                                                const float* __restrict__ kp,
                                                const float* __restrict__ g1,
                                                const float* __restrict__ b1)
{
    __shared__ float kps[KPN][3];
    __shared__ float ws[8][NBH][KPN];
    __shared__ float s1s[D2], h1s[D2];
    const int t = threadIdx.x;
    if (t < KPN * 3) ((float*)kps)[t] = kp[t];
    if (t < D2) {
        float sc, sh;
        fin_calc(g_sum1[t], g_sq1[t], g1[t], b1[t], sc, sh);
        s1s[t] = sc; h1s[t] = sh;
    }
    __syncthreads();

    const int warp = t >> 5, lane = t & 31;
    const int n = blockIdx.x * 8 + warp;

    const float cx = xyz[n * 3 + 0], cy = xyz[n * 3 + 1], cz = xyz[n * 3 + 2];
    const int j = nidx[n * NBH + lane];
    const float rx = xyz[j * 3 + 0] - cx;
    const float ry = xyz[j * 3 + 1] - cy;
    const float rz = xyz[j * 3 + 2] - cz;

    unsigned mask = 0;
#pragma unroll
    for (int k = 0; k < KPN; k++) {
        float dx = rx - kps[k][0], dy = ry - kps[k][1], dz = rz - kps[k][2];
        float sq = dx * dx + dy * dy + dz * dz;
        float w = 1.0f - fsqrt_approx(sq) * INV_INFL;
        w = w > 0.f ? w : 0.f;
        ws[warp][lane][k] = w;
        if (w > 0.f) mask |= (1u << k);
    }
    __syncwarp();

    const float sc0 = s1s[2 * lane], sc1 = s1s[2 * lane + 1];
    const float sh0 = h1s[2 * lane], sh1 = h1s[2 * lane + 1];
    const float2* x1v = (const float2*)g_x1;

    float fk0[KPN], fk1[KPN];
#pragma unroll
    for (int k = 0; k < KPN; k++) { fk0[k] = 0.f; fk1[k] = 0.f; }

    for (int h = 0; h < NBH; h++) {
        unsigned mh = __shfl_sync(0xffffffffu, mask, h);
        if (!mh) continue;                                 /* warp-uniform */
        int jj = __shfl_sync(0xffffffffu, j, h);
        float2 v = x1v[(size_t)jj * 32 + lane];
        float a = v.x * sc0 + sh0; a = a > 0.f ? a : SLOPE * a;
        float b = v.y * sc1 + sh1; b = b > 0.f ? b : SLOPE * b;
        while (mh) {
            int k = __ffs(mh) - 1; mh &= mh - 1;
            float w = ws[warp][h][k];
            fk0[k] += w * a;
            fk1[k] += w * b;
        }
    }

    bf16* oh = g_fk_hi + (size_t)n * FKDIM;
    bf16* ol = g_fk_lo + (size_t)n * FKDIM;
#pragma unroll
    for (int k = 0; k < KPN; k++) {
        union { bf16 b[2]; uint32_t u; } H, L;
        bf16 h0 = __float2bfloat16(fk0[k]), h1 = __float2bfloat16(fk1[k]);
        H.b[0] = h0; H.b[1] = h1;
        L.b[0] = __float2bfloat16(fk0[k] - __bfloat162float(h0));
        L.b[1] = __float2bfloat16(fk1[k] - __bfloat162float(h1));
        *(uint32_t*)(oh + k * 64 + 2 * lane) = H.u;
        *(uint32_t*)(ol + k * 64 + 2 * lane) = L.u;
    }
}

/* ------------------------- final epilogue (inline fin2 + finsc) ---------- */
__global__ __launch_bounds__(256) void k_epilogue(float* __restrict__ out,
                                                  const float* __restrict__ gsc,
                                                  const float* __restrict__ bsc,
                                                  const float* __restrict__ g2,
                                                  const float* __restrict__ b2)
{
    __shared__ float s2[COUT], h2[COUT], ss[COUT], hs[COUT];
    const int t = threadIdx.x;
    {
        float sc, sh;
        fin_calc(g_sum2[t], g_sq2[t], g2[t], b2[t], sc, sh);
        s2[t] = sc; h2[t] = sh;
        fin_calc(g_sumsc[t], g_sqsc[t], gsc[t], bsc[t], sc, sh);
        ss[t] = sc; hs[t] = sh;
    }
    __syncthreads();

    const int idx = blockIdx.x * 256 + t;          /* float4 index */
    const int c4 = (idx & 63) * 4;

    float4 x = ((float4*)out)[idx];
    float4 s = ((const float4*)g_sc)[idx];
    float v0 = x.x * s2[c4 + 0] + h2[c4 + 0]; v0 = v0 > 0.f ? v0 : SLOPE * v0;
    float v1 = x.y * s2[c4 + 1] + h2[c4 + 1]; v1 = v1 > 0.f ? v1 : SLOPE * v1;
    float v2 = x.z * s2[c4 + 2] + h2[c4 + 2]; v2 = v2 > 0.f ? v2 : SLOPE * v2;
    float v3 = x.w * s2[c4 + 3] + h2[c4 + 3]; v3 = v3 > 0.f ? v3 : SLOPE * v3;
    float4 r;
    r.x = v0 + s.x * ss[c4 + 0] + hs[c4 + 0];
    r.y = v1 + s.y * ss[c4 + 1] + hs[c4 + 1];
    r.z = v2 + s.z * ss[c4 + 2] + hs[c4 + 2];
    r.w = v3 + s.w * ss[c4 + 3] + hs[c4 + 3];
    ((float4*)out)[idx] = r;
}

/* ------------------------- launch ---------------------------------------- */
extern "C" void kernel_launch(void* const* d_in, const int* in_sizes, int n_in,
                              void* d_out, int out_size)
{
    const float* feats = (const float*)d_in[0];
    const float* xyz   = (const float*)d_in[1];
    const int*   nidx  = (const int*)d_in[3];
    const float* W1    = (const float*)d_in[4];
    const float* g1    = (const float*)d_in[5];
    const float* b1    = (const float*)d_in[6];
    const float* kp    = (const float*)d_in[7];
    const float* kpw   = (const float*)d_in[8];
    const float* W2    = (const float*)d_in[9];
    const float* g2    = (const float*)d_in[10];
    const float* b2    = (const float*)d_in[11];
    const float* Wsc   = (const float*)d_in[12];
    const float* gsc   = (const float*)d_in[13];
    const float* bsc   = (const float*)d_in[14];
    float* out = (float*)d_out;

    static bool attr_done = false;
    if (!attr_done) {
        cudaFuncSetAttribute(k_gemm_u1sc, cudaFuncAttributeMaxDynamicSharedMemorySize, GEMM_SMEM);
        cudaFuncSetAttribute(k_gemm_fk,   cudaFuncAttributeMaxDynamicSharedMemorySize, GEMM_SMEM);
        cudaFuncSetAttribute(k_gemm_u2,   cudaFuncAttributeMaxDynamicSharedMemorySize, GEMM_SMEM);
        attr_done = true;
    }

    /* 1: zero + feats split + weight split */
    k_prep<<<10465, 256>>>(feats, W1, Wsc, kpw, W2);

    /* 2: unary1 + shortcut + both fused stats */
    k_gemm_u1sc<<<dim3(NPTS / 128, 5), 256, GEMM_SMEM>>>();

    /* 3: kpconv (computes BN1 affine inline from sums) */
    k_kpconv<<<NPTS / 8, 256>>>(xyz, nidx, kp, g1, b1);

    /* 4: fk @ kpw -> xmid (bf16 split) */
    k_gemm_fk<<<dim3(NPTS / 128, 1), 256, GEMM_SMEM>>>();

    /* 5: unary2 + fused stats2 */
    k_gemm_u2<<<dim3(NPTS / 128, 4), 256, GEMM_SMEM>>>(out);

    /* 6: epilogue (computes BN2 + BNsc affines inline from sums) */
    k_epilogue<<<(NPTS * (COUT / 4)) / 256, 256>>>(out, gsc, bsc, g2, b2);
}

// round 15
// speedup vs baseline: 1.8058x; 1.1628x over previous
#include <cuda_runtime.h>
#include <cuda_bf16.h>
#include <cuda_fp16.h>
#include <cstdint>

#define NPTS 80000
#define NBH  32
#define KPN  15
#define CIN  128
#define D2   64
#define COUT 256
#define FKDIM (KPN*D2)   /* 960 */
#define INV_INFL 2.5f
#define EPSBN 1e-5f
#define SLOPE 0.2f

typedef __nv_bfloat16 bf16;

/* ------------------------- device scratch ------------------------------- */
/* Referenced ONLY from device code (host-side &__device__ = ATS trap). */
__device__ float g_x1[(size_t)NPTS*D2];
__device__ float g_sc[(size_t)NPTS*COUT];
__device__ bf16  g_feats_hi[(size_t)NPTS*CIN], g_feats_lo[(size_t)NPTS*CIN];
__device__ __half g_fk16[(size_t)NPTS*FKDIM];          /* single f16 plane */
__device__ bf16  g_xmid_hi[(size_t)NPTS*D2],  g_xmid_lo[(size_t)NPTS*D2];

__device__ bf16 g_W1t_hi[D2*CIN],   g_W1t_lo[D2*CIN];
__device__ bf16 g_Wsct_hi[COUT*CIN],g_Wsct_lo[COUT*CIN];
__device__ __half g_kpwt16[D2*FKDIM];                   /* single f16 plane */
__device__ bf16 g_W2t_hi[COUT*D2],  g_W2t_lo[COUT*D2];

__device__ float g_sum1[D2],  g_sq1[D2];
__device__ float g_sumsc[COUT],g_sqsc[COUT];
__device__ float g_sum2[COUT], g_sq2[COUT];

/* ------------------------- ptx helpers ---------------------------------- */
__device__ __forceinline__ void mma16816(float* c, const uint32_t* a, const uint32_t* b) {
    asm volatile("mma.sync.aligned.m16n8k16.row.col.f32.bf16.bf16.f32 "
        "{%0,%1,%2,%3}, {%4,%5,%6,%7}, {%8,%9}, {%0,%1,%2,%3};"
        : "+f"(c[0]), "+f"(c[1]), "+f"(c[2]), "+f"(c[3])
        : "r"(a[0]), "r"(a[1]), "r"(a[2]), "r"(a[3]), "r"(b[0]), "r"(b[1]));
}
__device__ __forceinline__ void mma16816h(float* c, const uint32_t* a, const uint32_t* b) {
    asm volatile("mma.sync.aligned.m16n8k16.row.col.f32.f16.f16.f32 "
        "{%0,%1,%2,%3}, {%4,%5,%6,%7}, {%8,%9}, {%0,%1,%2,%3};"
        : "+f"(c[0]), "+f"(c[1]), "+f"(c[2]), "+f"(c[3])
        : "r"(a[0]), "r"(a[1]), "r"(a[2]), "r"(a[3]), "r"(b[0]), "r"(b[1]));
}
template<typename T>
__device__ __forceinline__ void ldmx4(uint32_t& r0, uint32_t& r1, uint32_t& r2,
                                      uint32_t& r3, const T* p) {
    uint32_t a = (uint32_t)__cvta_generic_to_shared(p);
    asm volatile("ldmatrix.sync.aligned.m8n8.x4.shared.b16 {%0,%1,%2,%3}, [%4];"
        : "=r"(r0), "=r"(r1), "=r"(r2), "=r"(r3) : "r"(a));
}
__device__ __forceinline__ void cpasync16(void* s, const void* g) {
    uint32_t sa = (uint32_t)__cvta_generic_to_shared(s);
    asm volatile("cp.async.ca.shared.global [%0], [%1], 16;" :: "r"(sa), "l"(g) : "memory");
}
#define CP_COMMIT() asm volatile("cp.async.commit_group;" ::: "memory")
#define CP_WAIT1()  asm volatile("cp.async.wait_group 1;" ::: "memory")
#define CP_WAIT0()  asm volatile("cp.async.wait_group 0;" ::: "memory")

/* ------------------------- merged prep kernel --------------------------- */
__device__ __forceinline__ void split_store(float v, bf16* hi, bf16* lo, size_t i) {
    bf16 h = __float2bfloat16(v);
    hi[i] = h;
    lo[i] = __float2bfloat16(v - __bfloat162float(h));
}

/* grid = 10465: [0,10000) feats, [10000,10464) weights, 10464 zero-stats */
__global__ __launch_bounds__(256) void k_prep(const float* __restrict__ f,
                                              const float* __restrict__ W1,
                                              const float* __restrict__ Wsc,
                                              const float* __restrict__ kpw,
                                              const float* __restrict__ W2)
{
    const int b = blockIdx.x, t = threadIdx.x;
    if (b < 10000) {
        int i4 = b * 256 + t;                           /* < 2,560,000 */
        float4 v = ((const float4*)f)[i4];
        bf16 h0 = __float2bfloat16(v.x), h1 = __float2bfloat16(v.y);
        bf16 h2 = __float2bfloat16(v.z), h3 = __float2bfloat16(v.w);
        union { bf16 b_[4]; uint2 u; } H, L;
        H.b_[0] = h0; H.b_[1] = h1; H.b_[2] = h2; H.b_[3] = h3;
        L.b_[0] = __float2bfloat16(v.x - __bfloat162float(h0));
        L.b_[1] = __float2bfloat16(v.y - __bfloat162float(h1));
        L.b_[2] = __float2bfloat16(v.z - __bfloat162float(h2));
        L.b_[3] = __float2bfloat16(v.w - __bfloat162float(h3));
        ((uint2*)g_feats_hi)[i4] = H.u;
        ((uint2*)g_feats_lo)[i4] = L.u;
    } else if (b < 10464) {
        int i = (b - 10000) * 256 + t;                  /* < 118784 */
        if (i < 8192) {                                 /* W1t [64,128] */
            int e = i >> 7, k = i & 127;
            split_store(W1[k * D2 + e], g_W1t_hi, g_W1t_lo, i);
        } else if (i < 40960) {                         /* Wsct [256,128] */
            int j = i - 8192; int e = j >> 7, k = j & 127;
            split_store(Wsc[k * COUT + e], g_Wsct_hi, g_Wsct_lo, j);
        } else if (i < 102400) {                        /* kpwt16 [64,960] */
            int j = i - 40960; int e = j / FKDIM, kd = j % FKDIM;
            g_kpwt16[j] = __float2half(kpw[(size_t)kd * D2 + e]);
        } else {                                        /* W2t [256,64] */
            int j = i - 102400; int e = j >> 6, k = j & 63;
            split_store(W2[k * COUT + e], g_W2t_hi, g_W2t_lo, j);
        }
    } else {
        if (t < D2) { g_sum1[t] = 0.f; g_sq1[t] = 0.f; }
        g_sumsc[t] = 0.f; g_sqsc[t] = 0.f;
        g_sum2[t]  = 0.f; g_sq2[t]  = 0.f;
    }
}

/* inline BN finalize from sums */
__device__ __forceinline__ void fin_calc(float sum, float sq, float g, float b,
                                         float& scale, float& shift)
{
    float m = sum * (1.0f / NPTS);
    float v = sq * (1.0f / NPTS) - m * m;
    float s = g * rsqrtf(v + EPSBN);
    scale = s;
    shift = b - m * s;
}

/* ------------------------- HMMA split-bf16 GEMM (u1sc, u2) --------------- */
#define AST 40
#define BUF_ELEMS 15360
#define OFF_AL 5120
#define OFF_BH 10240
#define OFF_BL 12800
#define GEMM_SMEM 61440

template<int KTOT>
__device__ __forceinline__ void mmagemm_body(
    const bf16* __restrict__ Ahi, const bf16* __restrict__ Alo,
    const bf16* __restrict__ Bhi, const bf16* __restrict__ Blo,
    float* __restrict__ Cf, int ldc,
    float* __restrict__ sumP, float* __restrict__ sqP, int n0)
{
    extern __shared__ __align__(16) bf16 smem[];

    const int t = threadIdx.x, lane = t & 31, wid = t >> 5;
    const int wm = wid & 3, wn = wid >> 2;
    const int m0 = blockIdx.x * 128;
    const int gr = lane >> 2, gc2 = (lane & 3) * 2;

    const int arow0 = t >> 2, ac8 = (t & 3) * 8;
    const int brow = t >> 2,  bc8 = (t & 3) * 8;

    const int rAf  = wm * 32 + (lane & 15);
    const int kA8  = (lane >> 4) * 8;
    const int rBf  = wn * 32 + (lane & 7) + ((lane & 16) ? 8 : 0);
    const int kB8  = ((lane >> 3) & 1) * 8;

    float acc[2][4][4];
#pragma unroll
    for (int i = 0; i < 2; i++)
#pragma unroll
        for (int j = 0; j < 4; j++)
#pragma unroll
            for (int q = 0; q < 4; q++) acc[i][j][q] = 0.f;

    constexpr int NCH = KTOT / 32;

    auto issue = [&](int kc) {
        bf16* buf = smem + (kc & 1) * BUF_ELEMS;
#pragma unroll
        for (int it = 0; it < 2; it++) {
            int row = arow0 + it * 64;
            size_t gsrc = (size_t)(m0 + row) * KTOT + kc * 32 + ac8;
            cpasync16(buf + row * AST + ac8, Ahi + gsrc);
            cpasync16(buf + OFF_AL + row * AST + ac8, Alo + gsrc);
        }
        {
            size_t gsrc = (size_t)(n0 + brow) * KTOT + kc * 32 + bc8;
            cpasync16(buf + OFF_BH + brow * AST + bc8, Bhi + gsrc);
            cpasync16(buf + OFF_BL + brow * AST + bc8, Blo + gsrc);
        }
        CP_COMMIT();
    };

    issue(0);

    for (int kc = 0; kc < NCH; kc++) {
        if (kc + 1 < NCH) { issue(kc + 1); CP_WAIT1(); }
        else              { CP_WAIT0(); }
        __syncthreads();

        const bf16* sAh = smem + (kc & 1) * BUF_ELEMS;
        const bf16* sAl = sAh + OFF_AL;
        const bf16* sBh = sAh + OFF_BH;
        const bf16* sBl = sAh + OFF_BL;

#pragma unroll
        for (int kk = 0; kk < 2; kk++) {
            const int ke = kk * 16;
            uint32_t ah[2][4], al[2][4], bh[4][2], bl[4][2];
#pragma unroll
            for (int mt = 0; mt < 2; mt++) {
                ldmx4(ah[mt][0], ah[mt][1], ah[mt][2], ah[mt][3],
                      sAh + (rAf + mt * 16) * AST + ke + kA8);
                ldmx4(al[mt][0], al[mt][1], al[mt][2], al[mt][3],
                      sAl + (rAf + mt * 16) * AST + ke + kA8);
            }
#pragma unroll
            for (int p = 0; p < 2; p++) {
                ldmx4(bh[2*p][0], bh[2*p][1], bh[2*p+1][0], bh[2*p+1][1],
                      sBh + (rBf + p * 16) * AST + ke + kB8);
                ldmx4(bl[2*p][0], bl[2*p][1], bl[2*p+1][0], bl[2*p+1][1],
                      sBl + (rBf + p * 16) * AST + ke + kB8);
            }
#pragma unroll
            for (int mt = 0; mt < 2; mt++)
#pragma unroll
                for (int nt = 0; nt < 4; nt++) {
                    mma16816(acc[mt][nt], ah[mt], bh[nt]);
                    mma16816(acc[mt][nt], ah[mt], bl[nt]);
                    mma16816(acc[mt][nt], al[mt], bh[nt]);
                }
        }
        __syncthreads();
    }

    const int rbase = m0 + wm * 32 + gr;
    const int cbase = wn * 32 + gc2;

    /* C stores + fused stats */
#pragma unroll
    for (int mt = 0; mt < 2; mt++)
#pragma unroll
        for (int nt = 0; nt < 4; nt++) {
            int r0 = rbase + mt * 16, r1 = r0 + 8;
            int cc = n0 + cbase + nt * 8;
            *(float2*)(Cf + (size_t)r0 * ldc + cc) =
                make_float2(acc[mt][nt][0], acc[mt][nt][1]);
            *(float2*)(Cf + (size_t)r1 * ldc + cc) =
                make_float2(acc[mt][nt][2], acc[mt][nt][3]);
        }

    float cs[8], cq[8];
#pragma unroll
    for (int nt = 0; nt < 4; nt++)
#pragma unroll
        for (int j = 0; j < 2; j++) {
            float v0 = acc[0][nt][j],     v1 = acc[0][nt][2 + j];
            float v2 = acc[1][nt][j],     v3 = acc[1][nt][2 + j];
            cs[nt * 2 + j] = v0 + v1 + v2 + v3;
            cq[nt * 2 + j] = v0 * v0 + v1 * v1 + v2 * v2 + v3 * v3;
        }
#pragma unroll
    for (int off = 4; off < 32; off <<= 1)
#pragma unroll
        for (int i = 0; i < 8; i++) {
            cs[i] += __shfl_xor_sync(0xffffffffu, cs[i], off);
            cq[i] += __shfl_xor_sync(0xffffffffu, cq[i], off);
        }

    float* fs = (float*)smem;
    if (t < 128) fs[t] = 0.f;
    __syncthreads();
    if ((lane & 28) == 0) {
#pragma unroll
        for (int nt = 0; nt < 4; nt++)
#pragma unroll
            for (int j = 0; j < 2; j++) {
                int col = wn * 32 + (lane & 3) * 2 + nt * 8 + j;
                atomicAdd(&fs[col],      cs[nt * 2 + j]);
                atomicAdd(&fs[64 + col], cq[nt * 2 + j]);
            }
    }
    __syncthreads();
    if (t < 64) {
        atomicAdd(&sumP[n0 + t], fs[t]);
        atomicAdd(&sqP[n0 + t],  fs[64 + t]);
    }
}

__global__ __launch_bounds__(256) void k_gemm_u1sc() {
    if (blockIdx.y == 0)
        mmagemm_body<128>(g_feats_hi, g_feats_lo, g_W1t_hi, g_W1t_lo,
                          g_x1, D2, g_sum1, g_sq1, 0);
    else
        mmagemm_body<128>(g_feats_hi, g_feats_lo, g_Wsct_hi, g_Wsct_lo,
                          g_sc, COUT, g_sumsc, g_sqsc, (blockIdx.y - 1) * 64);
}
__global__ __launch_bounds__(256) void k_gemm_u2(float* __restrict__ out) {
    mmagemm_body<64>(g_xmid_hi, g_xmid_lo, g_W2t_hi, g_W2t_lo,
                     out, COUT, g_sum2, g_sq2, blockIdx.y * 64);
}

/* ------------------------- fk GEMM: single-plane f16 --------------------- */
/* A = g_fk16 [NPTS, 960] f16, B = g_kpwt16 [64, 960] f16.
   One mma per k16. Output: split bf16 xmid. Static smem 30 KB. */
#define FBUF 7680     /* halves per buffer: A 128*40 + B 64*40 */
#define FOFF_B 5120

__global__ __launch_bounds__(256) void k_gemm_fk()
{
    __shared__ __align__(16) __half smem[2 * FBUF];

    const int t = threadIdx.x, lane = t & 31, wid = t >> 5;
    const int wm = wid & 3, wn = wid >> 2;
    const int m0 = blockIdx.x * 128;
    const int gr = lane >> 2, gc2 = (lane & 3) * 2;

    const int arow0 = t >> 2, ac8 = (t & 3) * 8;
    const int brow = t >> 2,  bc8 = (t & 3) * 8;

    const int rAf  = wm * 32 + (lane & 15);
    const int kA8  = (lane >> 4) * 8;
    const int rBf  = wn * 32 + (lane & 7) + ((lane & 16) ? 8 : 0);
    const int kB8  = ((lane >> 3) & 1) * 8;

    float acc[2][4][4];
#pragma unroll
    for (int i = 0; i < 2; i++)
#pragma unroll
        for (int j = 0; j < 4; j++)
#pragma unroll
            for (int q = 0; q < 4; q++) acc[i][j][q] = 0.f;

    constexpr int NCH = FKDIM / 32;    /* 30 */

    auto issue = [&](int kc) {
        __half* buf = smem + (kc & 1) * FBUF;
#pragma unroll
        for (int it = 0; it < 2; it++) {
            int row = arow0 + it * 64;
            cpasync16(buf + row * AST + ac8,
                      g_fk16 + (size_t)(m0 + row) * FKDIM + kc * 32 + ac8);
        }
        cpasync16(buf + FOFF_B + brow * AST + bc8,
                  g_kpwt16 + (size_t)brow * FKDIM + kc * 32 + bc8);
        CP_COMMIT();
    };

    issue(0);

    for (int kc = 0; kc < NCH; kc++) {
        if (kc + 1 < NCH) { issue(kc + 1); CP_WAIT1(); }
        else              { CP_WAIT0(); }
        __syncthreads();

        const __half* sA = smem + (kc & 1) * FBUF;
        const __half* sB = sA + FOFF_B;

#pragma unroll
        for (int kk = 0; kk < 2; kk++) {
            const int ke = kk * 16;
            uint32_t a[2][4], b[4][2];
#pragma unroll
            for (int mt = 0; mt < 2; mt++)
                ldmx4(a[mt][0], a[mt][1], a[mt][2], a[mt][3],
                      sA + (rAf + mt * 16) * AST + ke + kA8);
#pragma unroll
            for (int p = 0; p < 2; p++)
                ldmx4(b[2*p][0], b[2*p][1], b[2*p+1][0], b[2*p+1][1],
                      sB + (rBf + p * 16) * AST + ke + kB8);
#pragma unroll
            for (int mt = 0; mt < 2; mt++)
#pragma unroll
                for (int nt = 0; nt < 4; nt++)
                    mma16816h(acc[mt][nt], a[mt], b[nt]);
        }
        __syncthreads();
    }

    /* epilogue: split bf16 xmid */
    const int rbase = m0 + wm * 32 + gr;
    const int cbase = wn * 32 + gc2;
#pragma unroll
    for (int mt = 0; mt < 2; mt++)
#pragma unroll
        for (int nt = 0; nt < 4; nt++) {
            int cc = cbase + nt * 8;
#pragma unroll
            for (int half = 0; half < 2; half++) {
                int rr = rbase + mt * 16 + half * 8;
                float v0 = acc[mt][nt][half * 2 + 0];
                float v1 = acc[mt][nt][half * 2 + 1];
                union { bf16 b_[2]; uint32_t u; } H, L;
                bf16 h0 = __float2bfloat16(v0), h1 = __float2bfloat16(v1);
                H.b_[0] = h0; H.b_[1] = h1;
                L.b_[0] = __float2bfloat16(v0 - __bfloat162float(h0));
                L.b_[1] = __float2bfloat16(v1 - __bfloat162float(h1));
                *(uint32_t*)(g_xmid_hi + (size_t)rr * 64 + cc) = H.u;
                *(uint32_t*)(g_xmid_lo + (size_t)rr * 64 + cc) = L.u;
            }
        }
}

/* ------------------------- KPConv (sparse influence, inline fin1) -------- */
__device__ __forceinline__ float fsqrt_approx(float x) {
    float r; asm("sqrt.approx.f32 %0, %1;" : "=f"(r) : "f"(x)); return r;
}

__global__ __launch_bounds__(256) void k_kpconv(const float* __restrict__ xyz,
                                                const int* __restrict__ nidx,
                                                const float* __restrict__ kp,
                                                const float* __restrict__ g1,
                                                const float* __restrict__ b1)
{
    __shared__ float kps[KPN][3];
    __shared__ float ws[8][NBH][KPN];
    __shared__ float s1s[D2], h1s[D2];
    const int t = threadIdx.x;
    if (t < KPN * 3) ((float*)kps)[t] = kp[t];
    if (t < D2) {
        float sc, sh;
        fin_calc(g_sum1[t], g_sq1[t], g1[t], b1[t], sc, sh);
        s1s[t] = sc; h1s[t] = sh;
    }
    __syncthreads();

    const int warp = t >> 5, lane = t & 31;
    const int n = blockIdx.x * 8 + warp;

    const float cx = xyz[n * 3 + 0], cy = xyz[n * 3 + 1], cz = xyz[n * 3 + 2];
    const int j = nidx[n * NBH + lane];
    const float rx = xyz[j * 3 + 0] - cx;
    const float ry = xyz[j * 3 + 1] - cy;
    const float rz = xyz[j * 3 + 2] - cz;

    unsigned mask = 0;
#pragma unroll
    for (int k = 0; k < KPN; k++) {
        float dx = rx - kps[k][0], dy = ry - kps[k][1], dz = rz - kps[k][2];
        float sq = dx * dx + dy * dy + dz * dz;
        float w = 1.0f - fsqrt_approx(sq) * INV_INFL;
        w = w > 0.f ? w : 0.f;
        ws[warp][lane][k] = w;
        if (w > 0.f) mask |= (1u << k);
    }
    __syncwarp();

    const float sc0 = s1s[2 * lane], sc1 = s1s[2 * lane + 1];
    const float sh0 = h1s[2 * lane], sh1 = h1s[2 * lane + 1];
    const float2* x1v = (const float2*)g_x1;

    float fk0[KPN], fk1[KPN];
#pragma unroll
    for (int k = 0; k < KPN; k++) { fk0[k] = 0.f; fk1[k] = 0.f; }

    for (int h = 0; h < NBH; h++) {
        unsigned mh = __shfl_sync(0xffffffffu, mask, h);
        if (!mh) continue;                                 /* warp-uniform */
        int jj = __shfl_sync(0xffffffffu, j, h);
        float2 v = x1v[(size_t)jj * 32 + lane];
        float a = v.x * sc0 + sh0; a = a > 0.f ? a : SLOPE * a;
        float b = v.y * sc1 + sh1; b = b > 0.f ? b : SLOPE * b;
        while (mh) {
            int k = __ffs(mh) - 1; mh &= mh - 1;
            float w = ws[warp][h][k];
            fk0[k] += w * a;
            fk1[k] += w * b;
        }
    }

    __half2* o = (__half2*)(g_fk16 + (size_t)n * FKDIM);
#pragma unroll
    for (int k = 0; k < KPN; k++)
        o[k * 32 + lane] = __floats2half2_rn(fk0[k], fk1[k]);
}

/* ------------------------- final epilogue (inline fin2 + finsc) ---------- */
__global__ __launch_bounds__(256) void k_epilogue(float* __restrict__ out,
                                                  const float* __restrict__ gsc,
                                                  const float* __restrict__ bsc,
                                                  const float* __restrict__ g2,
                                                  const float* __restrict__ b2)
{
    __shared__ float s2[COUT], h2[COUT], ss[COUT], hs[COUT];
    const int t = threadIdx.x;
    {
        float sc, sh;
        fin_calc(g_sum2[t], g_sq2[t], g2[t], b2[t], sc, sh);
        s2[t] = sc; h2[t] = sh;
        fin_calc(g_sumsc[t], g_sqsc[t], gsc[t], bsc[t], sc, sh);
        ss[t] = sc; hs[t] = sh;
    }
    __syncthreads();

    const int idx = blockIdx.x * 256 + t;          /* float4 index */
    const int c4 = (idx & 63) * 4;

    float4 x = ((float4*)out)[idx];
    float4 s = ((const float4*)g_sc)[idx];
    float v0 = x.x * s2[c4 + 0] + h2[c4 + 0]; v0 = v0 > 0.f ? v0 : SLOPE * v0;
    float v1 = x.y * s2[c4 + 1] + h2[c4 + 1]; v1 = v1 > 0.f ? v1 : SLOPE * v1;
    float v2 = x.z * s2[c4 + 2] + h2[c4 + 2]; v2 = v2 > 0.f ? v2 : SLOPE * v2;
    float v3 = x.w * s2[c4 + 3] + h2[c4 + 3]; v3 = v3 > 0.f ? v3 : SLOPE * v3;
    float4 r;
    r.x = v0 + s.x * ss[c4 + 0] + hs[c4 + 0];
    r.y = v1 + s.y * ss[c4 + 1] + hs[c4 + 1];
    r.z = v2 + s.z * ss[c4 + 2] + hs[c4 + 2];
    r.w = v3 + s.w * ss[c4 + 3] + hs[c4 + 3];
    ((float4*)out)[idx] = r;
}

/* ------------------------- launch ---------------------------------------- */
extern "C" void kernel_launch(void* const* d_in, const int* in_sizes, int n_in,
                              void* d_out, int out_size)
{
    const float* feats = (const float*)d_in[0];
    const float* xyz   = (const float*)d_in[1];
    const int*   nidx  = (const int*)d_in[3];
    const float* W1    = (const float*)d_in[4];
    const float* g1    = (const float*)d_in[5];
    const float* b1    = (const float*)d_in[6];
    const float* kp    = (const float*)d_in[7];
    const float* kpw   = (const float*)d_in[8];
    const float* W2    = (const float*)d_in[9];
    const float* g2    = (const float*)d_in[10];
    const float* b2    = (const float*)d_in[11];
    const float* Wsc   = (const float*)d_in[12];
    const float* gsc   = (const float*)d_in[13];
    const float* bsc   = (const float*)d_in[14];
    float* out = (float*)d_out;

    static bool attr_done = false;
    if (!attr_done) {
        cudaFuncSetAttribute(k_gemm_u1sc, cudaFuncAttributeMaxDynamicSharedMemorySize, GEMM_SMEM);
        cudaFuncSetAttribute(k_gemm_u2,   cudaFuncAttributeMaxDynamicSharedMemorySize, GEMM_SMEM);
        attr_done = true;
    }

    k_prep<<<10465, 256>>>(feats, W1, Wsc, kpw, W2);

    k_gemm_u1sc<<<dim3(NPTS / 128, 5), 256, GEMM_SMEM>>>();

    k_kpconv<<<NPTS / 8, 256>>>(xyz, nidx, kp, g1, b1);

    k_gemm_fk<<<NPTS / 128, 256>>>();

    k_gemm_u2<<<dim3(NPTS / 128, 4), 256, GEMM_SMEM>>>(out);

    k_epilogue<<<(NPTS * (COUT / 4)) / 256, 256>>>(out, gsc, bsc, g2, b2);
}

// round 16
// speedup vs baseline: 1.8572x; 1.0285x over previous
#include <cuda_runtime.h>
#include <cuda_bf16.h>
#include <cuda_fp16.h>
#include <cstdint>

#define NPTS 80000
#define NBH  32
#define KPN  15
#define CIN  128
#define D2   64
#define COUT 256
#define FKDIM (KPN*D2)   /* 960 */
#define INV_INFL 2.5f
#define EPSBN 1e-5f
#define SLOPE 0.2f

typedef __nv_bfloat16 bf16;

/* ------------------------- device scratch ------------------------------- */
/* Referenced ONLY from device code (host-side &__device__ = ATS trap). */
__device__ __half g_x1h[(size_t)NPTS*D2];              /* pre-BN unary1, f16 */
__device__ __half g_sch[(size_t)NPTS*COUT];            /* pre-BN shortcut, f16 */
__device__ __half g_x2h[(size_t)NPTS*COUT];            /* pre-BN unary2, f16 */
__device__ bf16  g_feats_hi[(size_t)NPTS*CIN], g_feats_lo[(size_t)NPTS*CIN];
__device__ __half g_fk16[(size_t)NPTS*FKDIM];          /* single f16 plane */
__device__ bf16  g_xmid_hi[(size_t)NPTS*D2],  g_xmid_lo[(size_t)NPTS*D2];

__device__ bf16 g_W1t_hi[D2*CIN],   g_W1t_lo[D2*CIN];
__device__ bf16 g_Wsct_hi[COUT*CIN],g_Wsct_lo[COUT*CIN];
__device__ __half g_kpwt16[D2*FKDIM];
__device__ bf16 g_W2t_hi[COUT*D2],  g_W2t_lo[COUT*D2];

__device__ float g_sum1[D2],  g_sq1[D2];
__device__ float g_sumsc[COUT],g_sqsc[COUT];
__device__ float g_sum2[COUT], g_sq2[COUT];

/* ------------------------- ptx helpers ---------------------------------- */
__device__ __forceinline__ void mma16816(float* c, const uint32_t* a, const uint32_t* b) {
    asm volatile("mma.sync.aligned.m16n8k16.row.col.f32.bf16.bf16.f32 "
        "{%0,%1,%2,%3}, {%4,%5,%6,%7}, {%8,%9}, {%0,%1,%2,%3};"
        : "+f"(c[0]), "+f"(c[1]), "+f"(c[2]), "+f"(c[3])
        : "r"(a[0]), "r"(a[1]), "r"(a[2]), "r"(a[3]), "r"(b[0]), "r"(b[1]));
}
__device__ __forceinline__ void mma16816h(float* c, const uint32_t* a, const uint32_t* b) {
    asm volatile("mma.sync.aligned.m16n8k16.row.col.f32.f16.f16.f32 "
        "{%0,%1,%2,%3}, {%4,%5,%6,%7}, {%8,%9}, {%0,%1,%2,%3};"
        : "+f"(c[0]), "+f"(c[1]), "+f"(c[2]), "+f"(c[3])
        : "r"(a[0]), "r"(a[1]), "r"(a[2]), "r"(a[3]), "r"(b[0]), "r"(b[1]));
}
template<typename T>
__device__ __forceinline__ void ldmx4(uint32_t& r0, uint32_t& r1, uint32_t& r2,
                                      uint32_t& r3, const T* p) {
    uint32_t a = (uint32_t)__cvta_generic_to_shared(p);
    asm volatile("ldmatrix.sync.aligned.m8n8.x4.shared.b16 {%0,%1,%2,%3}, [%4];"
        : "=r"(r0), "=r"(r1), "=r"(r2), "=r"(r3) : "r"(a));
}
__device__ __forceinline__ void cpasync16(void* s, const void* g) {
    uint32_t sa = (uint32_t)__cvta_generic_to_shared(s);
    asm volatile("cp.async.ca.shared.global [%0], [%1], 16;" :: "r"(sa), "l"(g) : "memory");
}
#define CP_COMMIT() asm volatile("cp.async.commit_group;" ::: "memory")
#define CP_WAIT1()  asm volatile("cp.async.wait_group 1;" ::: "memory")
#define CP_WAIT0()  asm volatile("cp.async.wait_group 0;" ::: "memory")

/* ------------------------- merged prep kernel --------------------------- */
__device__ __forceinline__ void split_store(float v, bf16* hi, bf16* lo, size_t i) {
    bf16 h = __float2bfloat16(v);
    hi[i] = h;
    lo[i] = __float2bfloat16(v - __bfloat162float(h));
}

/* grid = 10465: [0,10000) feats, [10000,10464) weights, 10464 zero-stats */
__global__ __launch_bounds__(256) void k_prep(const float* __restrict__ f,
                                              const float* __restrict__ W1,
                                              const float* __restrict__ Wsc,
                                              const float* __restrict__ kpw,
                                              const float* __restrict__ W2)
{
    const int b = blockIdx.x, t = threadIdx.x;
    if (b < 10000) {
        int i4 = b * 256 + t;                           /* < 2,560,000 */
        float4 v = ((const float4*)f)[i4];
        bf16 h0 = __float2bfloat16(v.x), h1 = __float2bfloat16(v.y);
        bf16 h2 = __float2bfloat16(v.z), h3 = __float2bfloat16(v.w);
        union { bf16 b_[4]; uint2 u; } H, L;
        H.b_[0] = h0; H.b_[1] = h1; H.b_[2] = h2; H.b_[3] = h3;
        L.b_[0] = __float2bfloat16(v.x - __bfloat162float(h0));
        L.b_[1] = __float2bfloat16(v.y - __bfloat162float(h1));
        L.b_[2] = __float2bfloat16(v.z - __bfloat162float(h2));
        L.b_[3] = __float2bfloat16(v.w - __bfloat162float(h3));
        ((uint2*)g_feats_hi)[i4] = H.u;
        ((uint2*)g_feats_lo)[i4] = L.u;
    } else if (b < 10464) {
        int i = (b - 10000) * 256 + t;                  /* < 118784 */
        if (i < 8192) {                                 /* W1t [64,128] */
            int e = i >> 7, k = i & 127;
            split_store(W1[k * D2 + e], g_W1t_hi, g_W1t_lo, i);
        } else if (i < 40960) {                         /* Wsct [256,128] */
            int j = i - 8192; int e = j >> 7, k = j & 127;
            split_store(Wsc[k * COUT + e], g_Wsct_hi, g_Wsct_lo, j);
        } else if (i < 102400) {                        /* kpwt16 [64,960] */
            int j = i - 40960; int e = j / FKDIM, kd = j % FKDIM;
            g_kpwt16[j] = __float2half(kpw[(size_t)kd * D2 + e]);
        } else {                                        /* W2t [256,64] */
            int j = i - 102400; int e = j >> 6, k = j & 63;
            split_store(W2[k * COUT + e], g_W2t_hi, g_W2t_lo, j);
        }
    } else {
        if (t < D2) { g_sum1[t] = 0.f; g_sq1[t] = 0.f; }
        g_sumsc[t] = 0.f; g_sqsc[t] = 0.f;
        g_sum2[t]  = 0.f; g_sq2[t]  = 0.f;
    }
}

/* inline BN finalize from sums */
__device__ __forceinline__ void fin_calc(float sum, float sq, float g, float b,
                                         float& scale, float& shift)
{
    float m = sum * (1.0f / NPTS);
    float v = sq * (1.0f / NPTS) - m * m;
    float s = g * rsqrtf(v + EPSBN);
    scale = s;
    shift = b - m * s;
}

/* ------------------------- HMMA split-bf16 GEMM (u1sc, u2) --------------- */
/* MODE 0 output: f16 C plane (half2 stores) + fused fp32 stats. */
#define AST 40
#define BUF_ELEMS 15360
#define OFF_AL 5120
#define OFF_BH 10240
#define OFF_BL 12800
#define GEMM_SMEM 61440

template<int KTOT>
__device__ __forceinline__ void mmagemm_body(
    const bf16* __restrict__ Ahi, const bf16* __restrict__ Alo,
    const bf16* __restrict__ Bhi, const bf16* __restrict__ Blo,
    __half* __restrict__ Cf, int ldc,
    float* __restrict__ sumP, float* __restrict__ sqP, int n0)
{
    extern __shared__ __align__(16) bf16 smem[];

    const int t = threadIdx.x, lane = t & 31, wid = t >> 5;
    const int wm = wid & 3, wn = wid >> 2;
    const int m0 = blockIdx.x * 128;
    const int gr = lane >> 2, gc2 = (lane & 3) * 2;

    const int arow0 = t >> 2, ac8 = (t & 3) * 8;
    const int brow = t >> 2,  bc8 = (t & 3) * 8;

    const int rAf  = wm * 32 + (lane & 15);
    const int kA8  = (lane >> 4) * 8;
    const int rBf  = wn * 32 + (lane & 7) + ((lane & 16) ? 8 : 0);
    const int kB8  = ((lane >> 3) & 1) * 8;

    float acc[2][4][4];
#pragma unroll
    for (int i = 0; i < 2; i++)
#pragma unroll
        for (int j = 0; j < 4; j++)
#pragma unroll
            for (int q = 0; q < 4; q++) acc[i][j][q] = 0.f;

    constexpr int NCH = KTOT / 32;

    auto issue = [&](int kc) {
        bf16* buf = smem + (kc & 1) * BUF_ELEMS;
#pragma unroll
        for (int it = 0; it < 2; it++) {
            int row = arow0 + it * 64;
            size_t gsrc = (size_t)(m0 + row) * KTOT + kc * 32 + ac8;
            cpasync16(buf + row * AST + ac8, Ahi + gsrc);
            cpasync16(buf + OFF_AL + row * AST + ac8, Alo + gsrc);
        }
        {
            size_t gsrc = (size_t)(n0 + brow) * KTOT + kc * 32 + bc8;
            cpasync16(buf + OFF_BH + brow * AST + bc8, Bhi + gsrc);
            cpasync16(buf + OFF_BL + brow * AST + bc8, Blo + gsrc);
        }
        CP_COMMIT();
    };

    issue(0);

    for (int kc = 0; kc < NCH; kc++) {
        if (kc + 1 < NCH) { issue(kc + 1); CP_WAIT1(); }
        else              { CP_WAIT0(); }
        __syncthreads();

        const bf16* sAh = smem + (kc & 1) * BUF_ELEMS;
        const bf16* sAl = sAh + OFF_AL;
        const bf16* sBh = sAh + OFF_BH;
        const bf16* sBl = sAh + OFF_BL;

#pragma unroll
        for (int kk = 0; kk < 2; kk++) {
            const int ke = kk * 16;
            uint32_t ah[2][4], al[2][4], bh[4][2], bl[4][2];
#pragma unroll
            for (int mt = 0; mt < 2; mt++) {
                ldmx4(ah[mt][0], ah[mt][1], ah[mt][2], ah[mt][3],
                      sAh + (rAf + mt * 16) * AST + ke + kA8);
                ldmx4(al[mt][0], al[mt][1], al[mt][2], al[mt][3],
                      sAl + (rAf + mt * 16) * AST + ke + kA8);
            }
#pragma unroll
            for (int p = 0; p < 2; p++) {
                ldmx4(bh[2*p][0], bh[2*p][1], bh[2*p+1][0], bh[2*p+1][1],
                      sBh + (rBf + p * 16) * AST + ke + kB8);
                ldmx4(bl[2*p][0], bl[2*p][1], bl[2*p+1][0], bl[2*p+1][1],
                      sBl + (rBf + p * 16) * AST + ke + kB8);
            }
#pragma unroll
            for (int mt = 0; mt < 2; mt++)
#pragma unroll
                for (int nt = 0; nt < 4; nt++) {
                    mma16816(acc[mt][nt], ah[mt], bh[nt]);
                    mma16816(acc[mt][nt], ah[mt], bl[nt]);
                    mma16816(acc[mt][nt], al[mt], bh[nt]);
                }
        }
        __syncthreads();
    }

    const int rbase = m0 + wm * 32 + gr;
    const int cbase = wn * 32 + gc2;

    /* C stores (f16) + fused fp32 stats */
#pragma unroll
    for (int mt = 0; mt < 2; mt++)
#pragma unroll
        for (int nt = 0; nt < 4; nt++) {
            int r0 = rbase + mt * 16, r1 = r0 + 8;
            int cc = n0 + cbase + nt * 8;
            *(__half2*)(Cf + (size_t)r0 * ldc + cc) =
                __floats2half2_rn(acc[mt][nt][0], acc[mt][nt][1]);
            *(__half2*)(Cf + (size_t)r1 * ldc + cc) =
                __floats2half2_rn(acc[mt][nt][2], acc[mt][nt][3]);
        }

    float cs[8], cq[8];
#pragma unroll
    for (int nt = 0; nt < 4; nt++)
#pragma unroll
        for (int j = 0; j < 2; j++) {
            float v0 = acc[0][nt][j],     v1 = acc[0][nt][2 + j];
            float v2 = acc[1][nt][j],     v3 = acc[1][nt][2 + j];
            cs[nt * 2 + j] = v0 + v1 + v2 + v3;
            cq[nt * 2 + j] = v0 * v0 + v1 * v1 + v2 * v2 + v3 * v3;
        }
#pragma unroll
    for (int off = 4; off < 32; off <<= 1)
#pragma unroll
        for (int i = 0; i < 8; i++) {
            cs[i] += __shfl_xor_sync(0xffffffffu, cs[i], off);
            cq[i] += __shfl_xor_sync(0xffffffffu, cq[i], off);
        }

    float* fs = (float*)smem;
    if (t < 128) fs[t] = 0.f;
    __syncthreads();
    if ((lane & 28) == 0) {
#pragma unroll
        for (int nt = 0; nt < 4; nt++)
#pragma unroll
            for (int j = 0; j < 2; j++) {
                int col = wn * 32 + (lane & 3) * 2 + nt * 8 + j;
                atomicAdd(&fs[col],      cs[nt * 2 + j]);
                atomicAdd(&fs[64 + col], cq[nt * 2 + j]);
            }
    }
    __syncthreads();
    if (t < 64) {
        atomicAdd(&sumP[n0 + t], fs[t]);
        atomicAdd(&sqP[n0 + t],  fs[64 + t]);
    }
}

__global__ __launch_bounds__(256) void k_gemm_u1sc() {
    if (blockIdx.y == 0)
        mmagemm_body<128>(g_feats_hi, g_feats_lo, g_W1t_hi, g_W1t_lo,
                          g_x1h, D2, g_sum1, g_sq1, 0);
    else
        mmagemm_body<128>(g_feats_hi, g_feats_lo, g_Wsct_hi, g_Wsct_lo,
                          g_sch, COUT, g_sumsc, g_sqsc, (blockIdx.y - 1) * 64);
}
__global__ __launch_bounds__(256) void k_gemm_u2() {
    mmagemm_body<64>(g_xmid_hi, g_xmid_lo, g_W2t_hi, g_W2t_lo,
                     g_x2h, COUT, g_sum2, g_sq2, blockIdx.y * 64);
}

/* ------------------------- fk GEMM: single-plane f16 --------------------- */
#define FBUF 7680
#define FOFF_B 5120

__global__ __launch_bounds__(256) void k_gemm_fk()
{
    __shared__ __align__(16) __half smem[2 * FBUF];

    const int t = threadIdx.x, lane = t & 31, wid = t >> 5;
    const int wm = wid & 3, wn = wid >> 2;
    const int m0 = blockIdx.x * 128;
    const int gr = lane >> 2, gc2 = (lane & 3) * 2;

    const int arow0 = t >> 2, ac8 = (t & 3) * 8;
    const int brow = t >> 2,  bc8 = (t & 3) * 8;

    const int rAf  = wm * 32 + (lane & 15);
    const int kA8  = (lane >> 4) * 8;
    const int rBf  = wn * 32 + (lane & 7) + ((lane & 16) ? 8 : 0);
    const int kB8  = ((lane >> 3) & 1) * 8;

    float acc[2][4][4];
#pragma unroll
    for (int i = 0; i < 2; i++)
#pragma unroll
        for (int j = 0; j < 4; j++)
#pragma unroll
            for (int q = 0; q < 4; q++) acc[i][j][q] = 0.f;

    constexpr int NCH = FKDIM / 32;    /* 30 */

    auto issue = [&](int kc) {
        __half* buf = smem + (kc & 1) * FBUF;
#pragma unroll
        for (int it = 0; it < 2; it++) {
            int row = arow0 + it * 64;
            cpasync16(buf + row * AST + ac8,
                      g_fk16 + (size_t)(m0 + row) * FKDIM + kc * 32 + ac8);
        }
        cpasync16(buf + FOFF_B + brow * AST + bc8,
                  g_kpwt16 + (size_t)brow * FKDIM + kc * 32 + bc8);
        CP_COMMIT();
    };

    issue(0);

    for (int kc = 0; kc < NCH; kc++) {
        if (kc + 1 < NCH) { issue(kc + 1); CP_WAIT1(); }
        else              { CP_WAIT0(); }
        __syncthreads();

        const __half* sA = smem + (kc & 1) * FBUF;
        const __half* sB = sA + FOFF_B;

#pragma unroll
        for (int kk = 0; kk < 2; kk++) {
            const int ke = kk * 16;
            uint32_t a[2][4], b[4][2];
#pragma unroll
            for (int mt = 0; mt < 2; mt++)
                ldmx4(a[mt][0], a[mt][1], a[mt][2], a[mt][3],
                      sA + (rAf + mt * 16) * AST + ke + kA8);
#pragma unroll
            for (int p = 0; p < 2; p++)
                ldmx4(b[2*p][0], b[2*p][1], b[2*p+1][0], b[2*p+1][1],
                      sB + (rBf + p * 16) * AST + ke + kB8);
#pragma unroll
            for (int mt = 0; mt < 2; mt++)
#pragma unroll
                for (int nt = 0; nt < 4; nt++)
                    mma16816h(acc[mt][nt], a[mt], b[nt]);
        }
        __syncthreads();
    }

    /* epilogue: split bf16 xmid */
    const int rbase = m0 + wm * 32 + gr;
    const int cbase = wn * 32 + gc2;
#pragma unroll
    for (int mt = 0; mt < 2; mt++)
#pragma unroll
        for (int nt = 0; nt < 4; nt++) {
            int cc = cbase + nt * 8;
#pragma unroll
            for (int half = 0; half < 2; half++) {
                int rr = rbase + mt * 16 + half * 8;
                float v0 = acc[mt][nt][half * 2 + 0];
                float v1 = acc[mt][nt][half * 2 + 1];
                union { bf16 b_[2]; uint32_t u; } H, L;
                bf16 h0 = __float2bfloat16(v0), h1 = __float2bfloat16(v1);
                H.b_[0] = h0; H.b_[1] = h1;
                L.b_[0] = __float2bfloat16(v0 - __bfloat162float(h0));
                L.b_[1] = __float2bfloat16(v1 - __bfloat162float(h1));
                *(uint32_t*)(g_xmid_hi + (size_t)rr * 64 + cc) = H.u;
                *(uint32_t*)(g_xmid_lo + (size_t)rr * 64 + cc) = L.u;
            }
        }
}

/* ------------------------- KPConv (sparse influence, inline fin1) -------- */
__device__ __forceinline__ float fsqrt_approx(float x) {
    float r; asm("sqrt.approx.f32 %0, %1;" : "=f"(r) : "f"(x)); return r;
}

__global__ __launch_bounds__(256) void k_kpconv(const float* __restrict__ xyz,
                                                const int* __restrict__ nidx,
                                                const float* __restrict__ kp,
                                                const float* __restrict__ g1,
                                                const float* __restrict__ b1)
{
    __shared__ float kps[KPN][3];
    __shared__ float ws[8][NBH][KPN];
    __shared__ float s1s[D2], h1s[D2];
    const int t = threadIdx.x;
    if (t < KPN * 3) ((float*)kps)[t] = kp[t];
    if (t < D2) {
        float sc, sh;
        fin_calc(g_sum1[t], g_sq1[t], g1[t], b1[t], sc, sh);
        s1s[t] = sc; h1s[t] = sh;
    }
    __syncthreads();

    const int warp = t >> 5, lane = t & 31;
    const int n = blockIdx.x * 8 + warp;

    const float cx = xyz[n * 3 + 0], cy = xyz[n * 3 + 1], cz = xyz[n * 3 + 2];
    const int j = nidx[n * NBH + lane];
    const float rx = xyz[j * 3 + 0] - cx;
    const float ry = xyz[j * 3 + 1] - cy;
    const float rz = xyz[j * 3 + 2] - cz;

    unsigned mask = 0;
#pragma unroll
    for (int k = 0; k < KPN; k++) {
        float dx = rx - kps[k][0], dy = ry - kps[k][1], dz = rz - kps[k][2];
        float sq = dx * dx + dy * dy + dz * dz;
        float w = 1.0f - fsqrt_approx(sq) * INV_INFL;
        w = w > 0.f ? w : 0.f;
        ws[warp][lane][k] = w;
        if (w > 0.f) mask |= (1u << k);
    }
    __syncwarp();

    const float sc0 = s1s[2 * lane], sc1 = s1s[2 * lane + 1];
    const float sh0 = h1s[2 * lane], sh1 = h1s[2 * lane + 1];
    const __half2* x1v = (const __half2*)g_x1h;

    float fk0[KPN], fk1[KPN];
#pragma unroll
    for (int k = 0; k < KPN; k++) { fk0[k] = 0.f; fk1[k] = 0.f; }

    for (int h = 0; h < NBH; h++) {
        unsigned mh = __shfl_sync(0xffffffffu, mask, h);
        if (!mh) continue;                                 /* warp-uniform */
        int jj = __shfl_sync(0xffffffffu, j, h);
        float2 v = __half22float2(x1v[(size_t)jj * 32 + lane]);
        float a = v.x * sc0 + sh0; a = a > 0.f ? a : SLOPE * a;
        float b = v.y * sc1 + sh1; b = b > 0.f ? b : SLOPE * b;
        while (mh) {
            int k = __ffs(mh) - 1; mh &= mh - 1;
            float w = ws[warp][h][k];
            fk0[k] += w * a;
            fk1[k] += w * b;
        }
    }

    __half2* o = (__half2*)(g_fk16 + (size_t)n * FKDIM);
#pragma unroll
    for (int k = 0; k < KPN; k++)
        o[k * 32 + lane] = __floats2half2_rn(fk0[k], fk1[k]);
}

/* ------------------------- final epilogue (inline fin2 + finsc) ---------- */
__global__ __launch_bounds__(256) void k_epilogue(float* __restrict__ out,
                                                  const float* __restrict__ gsc,
                                                  const float* __restrict__ bsc,
                                                  const float* __restrict__ g2,
                                                  const float* __restrict__ b2)
{
    __shared__ float s2[COUT], h2[COUT], ss[COUT], hs[COUT];
    const int t = threadIdx.x;
    {
        float sc, sh;
        fin_calc(g_sum2[t], g_sq2[t], g2[t], b2[t], sc, sh);
        s2[t] = sc; h2[t] = sh;
        fin_calc(g_sumsc[t], g_sqsc[t], gsc[t], bsc[t], sc, sh);
        ss[t] = sc; hs[t] = sh;
    }
    __syncthreads();

    const int idx = blockIdx.x * 256 + t;          /* 4-channel index */
    const int c4 = (idx & 63) * 4;

    union { uint2 u; __half2 h[2]; } X, S;
    X.u = ((const uint2*)g_x2h)[idx];
    S.u = ((const uint2*)g_sch)[idx];
    float2 x01 = __half22float2(X.h[0]), x23 = __half22float2(X.h[1]);
    float2 s01 = __half22float2(S.h[0]), s23 = __half22float2(S.h[1]);

    float v0 = x01.x * s2[c4 + 0] + h2[c4 + 0]; v0 = v0 > 0.f ? v0 : SLOPE * v0;
    float v1 = x01.y * s2[c4 + 1] + h2[c4 + 1]; v1 = v1 > 0.f ? v1 : SLOPE * v1;
    float v2 = x23.x * s2[c4 + 2] + h2[c4 + 2]; v2 = v2 > 0.f ? v2 : SLOPE * v2;
    float v3 = x23.y * s2[c4 + 3] + h2[c4 + 3]; v3 = v3 > 0.f ? v3 : SLOPE * v3;
    float4 r;
    r.x = v0 + s01.x * ss[c4 + 0] + hs[c4 + 0];
    r.y = v1 + s01.y * ss[c4 + 1] + hs[c4 + 1];
    r.z = v2 + s23.x * ss[c4 + 2] + hs[c4 + 2];
    r.w = v3 + s23.y * ss[c4 + 3] + hs[c4 + 3];
    ((float4*)out)[idx] = r;
}

/* ------------------------- launch ---------------------------------------- */
extern "C" void kernel_launch(void* const* d_in, const int* in_sizes, int n_in,
                              void* d_out, int out_size)
{
    const float* feats = (const float*)d_in[0];
    const float* xyz   = (const float*)d_in[1];
    const int*   nidx  = (const int*)d_in[3];
    const float* W1    = (const float*)d_in[4];
    const float* g1    = (const float*)d_in[5];
    const float* b1    = (const float*)d_in[6];
    const float* kp    = (const float*)d_in[7];
    const float* kpw   = (const float*)d_in[8];
    const float* W2    = (const float*)d_in[9];
    const float* g2    = (const float*)d_in[10];
    const float* b2    = (const float*)d_in[11];
    const float* Wsc   = (const float*)d_in[12];
    const float* gsc   = (const float*)d_in[13];
    const float* bsc   = (const float*)d_in[14];
    float* out = (float*)d_out;

    static bool attr_done = false;
    if (!attr_done) {
        cudaFuncSetAttribute(k_gemm_u1sc, cudaFuncAttributeMaxDynamicSharedMemorySize, GEMM_SMEM);
        cudaFuncSetAttribute(k_gemm_u2,   cudaFuncAttributeMaxDynamicSharedMemorySize, GEMM_SMEM);
        attr_done = true;
    }

    k_prep<<<10465, 256>>>(feats, W1, Wsc, kpw, W2);

    k_gemm_u1sc<<<dim3(NPTS / 128, 5), 256, GEMM_SMEM>>>();

    k_kpconv<<<NPTS / 8, 256>>>(xyz, nidx, kp, g1, b1);

    k_gemm_fk<<<NPTS / 128, 256>>>();

    k_gemm_u2<<<dim3(NPTS / 128, 4), 256, GEMM_SMEM>>>();

    k_epilogue<<<(NPTS * (COUT / 4)) / 256, 256>>>(out, gsc, bsc, g2, b2);
}

// round 17
// speedup vs baseline: 2.0662x; 1.1125x over previous
#include <cuda_runtime.h>
#include <cuda_fp16.h>
#include <cstdint>

#define NPTS 80000
#define NBH  32
#define KPN  15
#define CIN  128
#define D2   64
#define COUT 256
#define FKDIM (KPN*D2)   /* 960 */
#define INV_INFL 2.5f
#define EPSBN 1e-5f
#define SLOPE 0.2f

/* ------------------------- device scratch ------------------------------- */
/* Referenced ONLY from device code (host-side &__device__ = ATS trap). */
__device__ __half g_feats16[(size_t)NPTS*CIN];
__device__ __half g_x1h[(size_t)NPTS*D2];
__device__ __half g_sch[(size_t)NPTS*COUT];
__device__ __half g_x2h[(size_t)NPTS*COUT];
__device__ __half g_fk16[(size_t)NPTS*FKDIM];
__device__ __half g_xmid16[(size_t)NPTS*D2];

__device__ __half g_W1t16[D2*CIN];
__device__ __half g_Wsct16[COUT*CIN];
__device__ __half g_kpwt16[D2*FKDIM];
__device__ __half g_W2t16[COUT*D2];

__device__ float g_sum1[D2],  g_sq1[D2];
__device__ float g_sumsc[COUT],g_sqsc[COUT];
__device__ float g_sum2[COUT], g_sq2[COUT];

/* ------------------------- ptx helpers ---------------------------------- */
__device__ __forceinline__ void mma16816h(float* c, const uint32_t* a, const uint32_t* b) {
    asm volatile("mma.sync.aligned.m16n8k16.row.col.f32.f16.f16.f32 "
        "{%0,%1,%2,%3}, {%4,%5,%6,%7}, {%8,%9}, {%0,%1,%2,%3};"
        : "+f"(c[0]), "+f"(c[1]), "+f"(c[2]), "+f"(c[3])
        : "r"(a[0]), "r"(a[1]), "r"(a[2]), "r"(a[3]), "r"(b[0]), "r"(b[1]));
}
__device__ __forceinline__ void ldmx4(uint32_t& r0, uint32_t& r1, uint32_t& r2,
                                      uint32_t& r3, const __half* p) {
    uint32_t a = (uint32_t)__cvta_generic_to_shared(p);
    asm volatile("ldmatrix.sync.aligned.m8n8.x4.shared.b16 {%0,%1,%2,%3}, [%4];"
        : "=r"(r0), "=r"(r1), "=r"(r2), "=r"(r3) : "r"(a));
}
__device__ __forceinline__ void cpasync16(void* s, const void* g) {
    uint32_t sa = (uint32_t)__cvta_generic_to_shared(s);
    asm volatile("cp.async.ca.shared.global [%0], [%1], 16;" :: "r"(sa), "l"(g) : "memory");
}
#define CP_COMMIT() asm volatile("cp.async.commit_group;" ::: "memory")
#define CP_WAIT1()  asm volatile("cp.async.wait_group 1;" ::: "memory")
#define CP_WAIT0()  asm volatile("cp.async.wait_group 0;" ::: "memory")

/* ------------------------- merged prep kernel --------------------------- */
/* grid = 10465: [0,10000) feats, [10000,10464) weights, 10464 zero-stats */
__global__ __launch_bounds__(256) void k_prep(const float* __restrict__ f,
                                              const float* __restrict__ W1,
                                              const float* __restrict__ Wsc,
                                              const float* __restrict__ kpw,
                                              const float* __restrict__ W2)
{
    const int b = blockIdx.x, t = threadIdx.x;
    if (b < 10000) {
        int i4 = b * 256 + t;                           /* < 2,560,000 */
        float4 v = ((const float4*)f)[i4];
        union { __half h[4]; uint2 u; } P;
        P.h[0] = __float2half(v.x); P.h[1] = __float2half(v.y);
        P.h[2] = __float2half(v.z); P.h[3] = __float2half(v.w);
        ((uint2*)g_feats16)[i4] = P.u;
    } else if (b < 10464) {
        int i = (b - 10000) * 256 + t;                  /* < 118784 */
        if (i < 8192) {                                 /* W1t [64,128] */
            int e = i >> 7, k = i & 127;
            g_W1t16[i] = __float2half(W1[k * D2 + e]);
        } else if (i < 40960) {                         /* Wsct [256,128] */
            int j = i - 8192; int e = j >> 7, k = j & 127;
            g_Wsct16[j] = __float2half(Wsc[k * COUT + e]);
        } else if (i < 102400) {                        /* kpwt16 [64,960] */
            int j = i - 40960; int e = j / FKDIM, kd = j % FKDIM;
            g_kpwt16[j] = __float2half(kpw[(size_t)kd * D2 + e]);
        } else {                                        /* W2t [256,64] */
            int j = i - 102400; int e = j >> 6, k = j & 63;
            g_W2t16[j] = __float2half(W2[k * COUT + e]);
        }
    } else {
        if (t < D2) { g_sum1[t] = 0.f; g_sq1[t] = 0.f; }
        g_sumsc[t] = 0.f; g_sqsc[t] = 0.f;
        g_sum2[t]  = 0.f; g_sq2[t]  = 0.f;
    }
}

/* inline BN finalize from sums */
__device__ __forceinline__ void fin_calc(float sum, float sq, float g, float b,
                                         float& scale, float& shift)
{
    float m = sum * (1.0f / NPTS);
    float v = sq * (1.0f / NPTS) - m * m;
    float s = g * rsqrtf(v + EPSBN);
    scale = s;
    shift = b - m * s;
}

/* ------------------------- unified single-f16 HMMA GEMM ------------------ */
/* Tile 128 x 64, 256 thr = 8 warps (4 m x 2 n), warp tile 32x32.
   Verified fragment addressing + cp.async double buffer (R15 fk kernel),
   generalized with n0 + optional fused BN stats.
   A [M, KTOT] f16, B [64-tile rows, KTOT] f16, C f16 plane. */
#define AST 40
#define FBUF 7680     /* halves per buffer: A 128*40 + B 64*40 */
#define FOFF_B 5120

template<int KTOT, int STATS>
__device__ __forceinline__ void hgemm_body(
    const __half* __restrict__ A, const __half* __restrict__ B,
    __half* __restrict__ C, int ldc,
    float* __restrict__ sumP, float* __restrict__ sqP, int n0)
{
    __shared__ __align__(16) __half smem[2 * FBUF];

    const int t = threadIdx.x, lane = t & 31, wid = t >> 5;
    const int wm = wid & 3, wn = wid >> 2;
    const int m0 = blockIdx.x * 128;
    const int gr = lane >> 2, gc2 = (lane & 3) * 2;

    const int arow0 = t >> 2, ac8 = (t & 3) * 8;
    const int brow = t >> 2,  bc8 = (t & 3) * 8;

    const int rAf  = wm * 32 + (lane & 15);
    const int kA8  = (lane >> 4) * 8;
    const int rBf  = wn * 32 + (lane & 7) + ((lane & 16) ? 8 : 0);
    const int kB8  = ((lane >> 3) & 1) * 8;

    float acc[2][4][4];
#pragma unroll
    for (int i = 0; i < 2; i++)
#pragma unroll
        for (int j = 0; j < 4; j++)
#pragma unroll
            for (int q = 0; q < 4; q++) acc[i][j][q] = 0.f;

    constexpr int NCH = KTOT / 32;

    auto issue = [&](int kc) {
        __half* buf = smem + (kc & 1) * FBUF;
#pragma unroll
        for (int it = 0; it < 2; it++) {
            int row = arow0 + it * 64;
            cpasync16(buf + row * AST + ac8,
                      A + (size_t)(m0 + row) * KTOT + kc * 32 + ac8);
        }
        cpasync16(buf + FOFF_B + brow * AST + bc8,
                  B + (size_t)(n0 + brow) * KTOT + kc * 32 + bc8);
        CP_COMMIT();
    };

    issue(0);

    for (int kc = 0; kc < NCH; kc++) {
        if (kc + 1 < NCH) { issue(kc + 1); CP_WAIT1(); }
        else              { CP_WAIT0(); }
        __syncthreads();

        const __half* sA = smem + (kc & 1) * FBUF;
        const __half* sB = sA + FOFF_B;

#pragma unroll
        for (int kk = 0; kk < 2; kk++) {
            const int ke = kk * 16;
            uint32_t a[2][4], b[4][2];
#pragma unroll
            for (int mt = 0; mt < 2; mt++)
                ldmx4(a[mt][0], a[mt][1], a[mt][2], a[mt][3],
                      sA + (rAf + mt * 16) * AST + ke + kA8);
#pragma unroll
            for (int p = 0; p < 2; p++)
                ldmx4(b[2*p][0], b[2*p][1], b[2*p+1][0], b[2*p+1][1],
                      sB + (rBf + p * 16) * AST + ke + kB8);
#pragma unroll
            for (int mt = 0; mt < 2; mt++)
#pragma unroll
                for (int nt = 0; nt < 4; nt++)
                    mma16816h(acc[mt][nt], a[mt], b[nt]);
        }
        __syncthreads();
    }

    const int rbase = m0 + wm * 32 + gr;
    const int cbase = wn * 32 + gc2;

    /* C stores (f16) */
#pragma unroll
    for (int mt = 0; mt < 2; mt++)
#pragma unroll
        for (int nt = 0; nt < 4; nt++) {
            int r0 = rbase + mt * 16, r1 = r0 + 8;
            int cc = n0 + cbase + nt * 8;
            *(__half2*)(C + (size_t)r0 * ldc + cc) =
                __floats2half2_rn(acc[mt][nt][0], acc[mt][nt][1]);
            *(__half2*)(C + (size_t)r1 * ldc + cc) =
                __floats2half2_rn(acc[mt][nt][2], acc[mt][nt][3]);
        }

    if (STATS) {
        float cs[8], cq[8];
#pragma unroll
        for (int nt = 0; nt < 4; nt++)
#pragma unroll
            for (int j = 0; j < 2; j++) {
                float v0 = acc[0][nt][j],     v1 = acc[0][nt][2 + j];
                float v2 = acc[1][nt][j],     v3 = acc[1][nt][2 + j];
                cs[nt * 2 + j] = v0 + v1 + v2 + v3;
                cq[nt * 2 + j] = v0 * v0 + v1 * v1 + v2 * v2 + v3 * v3;
            }
#pragma unroll
        for (int off = 4; off < 32; off <<= 1)
#pragma unroll
            for (int i = 0; i < 8; i++) {
                cs[i] += __shfl_xor_sync(0xffffffffu, cs[i], off);
                cq[i] += __shfl_xor_sync(0xffffffffu, cq[i], off);
            }

        float* fs = (float*)smem;
        if (t < 128) fs[t] = 0.f;
        __syncthreads();
        if ((lane & 28) == 0) {
#pragma unroll
            for (int nt = 0; nt < 4; nt++)
#pragma unroll
                for (int j = 0; j < 2; j++) {
                    int col = wn * 32 + (lane & 3) * 2 + nt * 8 + j;
                    atomicAdd(&fs[col],      cs[nt * 2 + j]);
                    atomicAdd(&fs[64 + col], cq[nt * 2 + j]);
                }
        }
        __syncthreads();
        if (t < 64) {
            atomicAdd(&sumP[n0 + t], fs[t]);
            atomicAdd(&sqP[n0 + t],  fs[64 + t]);
        }
    }
}

/* wrappers: globals bound in DEVICE code */
__global__ __launch_bounds__(256) void k_gemm_u1sc() {
    if (blockIdx.y == 0)
        hgemm_body<128, 1>(g_feats16, g_W1t16, g_x1h, D2, g_sum1, g_sq1, 0);
    else
        hgemm_body<128, 1>(g_feats16, g_Wsct16, g_sch, COUT,
                           g_sumsc, g_sqsc, (blockIdx.y - 1) * 64);
}
__global__ __launch_bounds__(256) void k_gemm_fk() {
    hgemm_body<960, 0>(g_fk16, g_kpwt16, g_xmid16, D2, nullptr, nullptr, 0);
}
__global__ __launch_bounds__(256) void k_gemm_u2() {
    hgemm_body<64, 1>(g_xmid16, g_W2t16, g_x2h, COUT,
                      g_sum2, g_sq2, blockIdx.y * 64);
}

/* ------------------------- KPConv (sparse influence, inline fin1) -------- */
__device__ __forceinline__ float fsqrt_approx(float x) {
    float r; asm("sqrt.approx.f32 %0, %1;" : "=f"(r) : "f"(x)); return r;
}

__global__ __launch_bounds__(256) void k_kpconv(const float* __restrict__ xyz,
                                                const int* __restrict__ nidx,
                                                const float* __restrict__ kp,
                                                const float* __restrict__ g1,
                                                const float* __restrict__ b1)
{
    __shared__ float kps[KPN][3];
    __shared__ float ws[8][NBH][KPN];
    __shared__ float s1s[D2], h1s[D2];
    const int t = threadIdx.x;
    if (t < KPN * 3) ((float*)kps)[t] = kp[t];
    if (t < D2) {
        float sc, sh;
        fin_calc(g_sum1[t], g_sq1[t], g1[t], b1[t], sc, sh);
        s1s[t] = sc; h1s[t] = sh;
    }
    __syncthreads();

    const int warp = t >> 5, lane = t & 31;
    const int n = blockIdx.x * 8 + warp;

    const float cx = xyz[n * 3 + 0], cy = xyz[n * 3 + 1], cz = xyz[n * 3 + 2];
    const int j = nidx[n * NBH + lane];
    const float rx = xyz[j * 3 + 0] - cx;
    const float ry = xyz[j * 3 + 1] - cy;
    const float rz = xyz[j * 3 + 2] - cz;

    unsigned mask = 0;
#pragma unroll
    for (int k = 0; k < KPN; k++) {
        float dx = rx - kps[k][0], dy = ry - kps[k][1], dz = rz - kps[k][2];
        float sq = dx * dx + dy * dy + dz * dz;
        float w = 1.0f - fsqrt_approx(sq) * INV_INFL;
        w = w > 0.f ? w : 0.f;
        ws[warp][lane][k] = w;
        if (w > 0.f) mask |= (1u << k);
    }
    __syncwarp();

    const float sc0 = s1s[2 * lane], sc1 = s1s[2 * lane + 1];
    const float sh0 = h1s[2 * lane], sh1 = h1s[2 * lane + 1];
    const __half2* x1v = (const __half2*)g_x1h;

    float fk0[KPN], fk1[KPN];
#pragma unroll
    for (int k = 0; k < KPN; k++) { fk0[k] = 0.f; fk1[k] = 0.f; }

    for (int h = 0; h < NBH; h++) {
        unsigned mh = __shfl_sync(0xffffffffu, mask, h);
        if (!mh) continue;                                 /* warp-uniform */
        int jj = __shfl_sync(0xffffffffu, j, h);
        float2 v = __half22float2(x1v[(size_t)jj * 32 + lane]);
        float a = v.x * sc0 + sh0; a = a > 0.f ? a : SLOPE * a;
        float b = v.y * sc1 + sh1; b = b > 0.f ? b : SLOPE * b;
        while (mh) {
            int k = __ffs(mh) - 1; mh &= mh - 1;
            float w = ws[warp][h][k];
            fk0[k] += w * a;
            fk1[k] += w * b;
        }
    }

    __half2* o = (__half2*)(g_fk16 + (size_t)n * FKDIM);
#pragma unroll
    for (int k = 0; k < KPN; k++)
        o[k * 32 + lane] = __floats2half2_rn(fk0[k], fk1[k]);
}

/* ------------------------- final epilogue (inline fin2 + finsc) ---------- */
__global__ __launch_bounds__(256) void k_epilogue(float* __restrict__ out,
                                                  const float* __restrict__ gsc,
                                                  const float* __restrict__ bsc,
                                                  const float* __restrict__ g2,
                                                  const float* __restrict__ b2)
{
    __shared__ float s2[COUT], h2[COUT], ss[COUT], hs[COUT];
    const int t = threadIdx.x;
    {
        float sc, sh;
        fin_calc(g_sum2[t], g_sq2[t], g2[t], b2[t], sc, sh);
        s2[t] = sc; h2[t] = sh;
        fin_calc(g_sumsc[t], g_sqsc[t], gsc[t], bsc[t], sc, sh);
        ss[t] = sc; hs[t] = sh;
    }
    __syncthreads();

    const int idx = blockIdx.x * 256 + t;          /* 4-channel index */
    const int c4 = (idx & 63) * 4;

    union { uint2 u; __half2 h[2]; } X, S;
    X.u = ((const uint2*)g_x2h)[idx];
    S.u = ((const uint2*)g_sch)[idx];
    float2 x01 = __half22float2(X.h[0]), x23 = __half22float2(X.h[1]);
    float2 s01 = __half22float2(S.h[0]), s23 = __half22float2(S.h[1]);

    float v0 = x01.x * s2[c4 + 0] + h2[c4 + 0]; v0 = v0 > 0.f ? v0 : SLOPE * v0;
    float v1 = x01.y * s2[c4 + 1] + h2[c4 + 1]; v1 = v1 > 0.f ? v1 : SLOPE * v1;
    float v2 = x23.x * s2[c4 + 2] + h2[c4 + 2]; v2 = v2 > 0.f ? v2 : SLOPE * v2;
    float v3 = x23.y * s2[c4 + 3] + h2[c4 + 3]; v3 = v3 > 0.f ? v3 : SLOPE * v3;
    float4 r;
    r.x = v0 + s01.x * ss[c4 + 0] + hs[c4 + 0];
    r.y = v1 + s01.y * ss[c4 + 1] + hs[c4 + 1];
    r.z = v2 + s23.x * ss[c4 + 2] + hs[c4 + 2];
    r.w = v3 + s23.y * ss[c4 + 3] + hs[c4 + 3];
    ((float4*)out)[idx] = r;
}

/* ------------------------- launch ---------------------------------------- */
extern "C" void kernel_launch(void* const* d_in, const int* in_sizes, int n_in,
                              void* d_out, int out_size)
{
    const float* feats = (const float*)d_in[0];
    const float* xyz   = (const float*)d_in[1];
    const int*   nidx  = (const int*)d_in[3];
    const float* W1    = (const float*)d_in[4];
    const float* g1    = (const float*)d_in[5];
    const float* b1    = (const float*)d_in[6];
    const float* kp    = (const float*)d_in[7];
    const float* kpw   = (const float*)d_in[8];
    const float* W2    = (const float*)d_in[9];
    const float* g2    = (const float*)d_in[10];
    const float* b2    = (const float*)d_in[11];
    const float* Wsc   = (const float*)d_in[12];
    const float* gsc   = (const float*)d_in[13];
    const float* bsc   = (const float*)d_in[14];
    float* out = (float*)d_out;

    k_prep<<<10465, 256>>>(feats, W1, Wsc, kpw, W2);

    k_gemm_u1sc<<<dim3(NPTS / 128, 5), 256>>>();

    k_kpconv<<<NPTS / 8, 256>>>(xyz, nidx, kp, g1, b1);

    k_gemm_fk<<<NPTS / 128, 256>>>();

    k_gemm_u2<<<dim3(NPTS / 128, 4), 256>>>();

    k_epilogue<<<(NPTS * (COUT / 4)) / 256, 256>>>(out, gsc, bsc, g2, b2);
}